// round 5
// baseline (speedup 1.0000x reference)
#include <cuda_runtime.h>
#include <cuda_bf16.h>
#include <math.h>
#include <stdint.h>

#define Bn 4
#define Cn 512
#define Ln 4096

// ---------------------------------------------------------------------------
// Scratch (static device globals; no allocation allowed)
// ---------------------------------------------------------------------------
__device__ float g_E[(size_t)Bn * Ln * Ln];                    // energy fp32 [b][i][j]
__device__ __nv_bfloat16 g_Qt_hi[(size_t)Bn * Ln * Cn];        // Q^T  [b][i][c]
__device__ __nv_bfloat16 g_Qt_lo[(size_t)Bn * Ln * Cn];
__device__ __nv_bfloat16 g_Kt_hi[(size_t)Bn * Ln * Cn];        // K^T  [b][j][c]
__device__ __nv_bfloat16 g_Kt_lo[(size_t)Bn * Ln * Cn];
__device__ __nv_bfloat16 g_V_hi[(size_t)Bn * Cn * Ln];         // V    [b][c][j]
__device__ __nv_bfloat16 g_V_lo[(size_t)Bn * Cn * Ln];
__device__ __nv_bfloat16 g_P_hi[(size_t)Bn * Ln * Ln];         // att  [b][i][j]
__device__ __nv_bfloat16 g_P_lo[(size_t)Bn * Ln * Ln];

// ---------------------------------------------------------------------------
// Base-ISA helpers (compute_103-safe: ldmatrix / mma.sync / cp.async)
// ---------------------------------------------------------------------------
__device__ __forceinline__ uint32_t smem_u32(const void* p) {
    uint32_t a;
    asm("{ .reg .u64 t; cvta.to.shared.u64 t, %1; cvt.u32.u64 %0, t; }" : "=r"(a) : "l"(p));
    return a;
}
__device__ __forceinline__ void ldsm_x4(uint32_t addr, uint32_t r[4]) {
    asm volatile("ldmatrix.sync.aligned.m8n8.x4.shared.b16 {%0,%1,%2,%3}, [%4];"
                 : "=r"(r[0]), "=r"(r[1]), "=r"(r[2]), "=r"(r[3]) : "r"(addr));
}
__device__ __forceinline__ void mma_bf16(float d[4], const uint32_t a[4], const uint32_t b[2]) {
    asm volatile("mma.sync.aligned.m16n8k16.row.col.f32.bf16.bf16.f32 "
                 "{%0,%1,%2,%3}, {%4,%5,%6,%7}, {%8,%9}, {%0,%1,%2,%3};"
                 : "+f"(d[0]), "+f"(d[1]), "+f"(d[2]), "+f"(d[3])
                 : "r"(a[0]), "r"(a[1]), "r"(a[2]), "r"(a[3]), "r"(b[0]), "r"(b[1]));
}
#define CP16(d, s) asm volatile("cp.async.cg.shared.global [%0], [%1], 16;" :: "r"(d), "l"(s))
#define CP_COMMIT() asm volatile("cp.async.commit_group;" ::: "memory")
#define CP_WAIT1()  asm volatile("cp.async.wait_group 1;" ::: "memory")
#define CP_WAIT0()  asm volatile("cp.async.wait_group 0;" ::: "memory")

__device__ __forceinline__ void split_bf16(float x, __nv_bfloat16& h, __nv_bfloat16& l) {
    h = __float2bfloat16(x);
    l = __float2bfloat16(x - __bfloat162float(h));
}

// ---------------------------------------------------------------------------
// smem geometry: 4 tiles (Ah, Al, Bh, Bl), 128 rows x 32 bf16 = 64 B rows,
// XOR-swizzled (conflict-free cp.async stores AND ldmatrix reads).
// Triple buffered: 3 x 32 KB = 96 KB -> still 2 CTAs/SM.
// ---------------------------------------------------------------------------
#define SW(o) ((o) ^ (((o) >> 3) & 0x30))
#define ROWB 64
#define TILE_B (128 * ROWB)        // 8192
#define OFF_AH 0
#define OFF_AL (1 * TILE_B)
#define OFF_BH (2 * TILE_B)
#define OFF_BL (3 * TILE_B)
#define BUF_B  (4 * TILE_B)        // 32768
#define NSTAGE 3
#define LM_OFF (NSTAGE * BUF_B)    // 98304
#define SMEM_BYTES (NSTAGE * BUF_B + 512)

// ---------------------------------------------------------------------------
// bf16x3 tensor-core GEMM, 128x128 tile, BK=32, 256 threads, 3-stage pipeline.
// FIRST: E[i][j] = (Qt[i][:] . Kt[j][:]) * scale + logmask[j]    (K = 512)
// !FIRST: out[c][i] = V[c][:] . P[i][:]                          (K = 4096)
// ---------------------------------------------------------------------------
template <bool FIRST>
__global__ __launch_bounds__(256) void mma_gemm_kernel(float* __restrict__ Dout,
                                                       const float* __restrict__ mask)
{
    constexpr int KTOT = FIRST ? Cn : Ln;
    constexpr int LD   = FIRST ? Cn : Ln;       // K-stride of A and B rows
    constexpr int NIT  = KTOT / 32;

    extern __shared__ char smem[];
    const uint32_t sbase = smem_u32(smem);
    const int tid = threadIdx.x;
    const int b = blockIdx.z;
    const int n0 = (FIRST ? blockIdx.x : blockIdx.y) * 128;
    const int m0 = (FIRST ? blockIdx.y : blockIdx.x) * 128;

    const __nv_bfloat16* Ah = (FIRST ? g_Qt_hi : g_V_hi) + ((size_t)b * (FIRST ? Ln : Cn) + m0) * LD;
    const __nv_bfloat16* Al = (FIRST ? g_Qt_lo : g_V_lo) + ((size_t)b * (FIRST ? Ln : Cn) + m0) * LD;
    const __nv_bfloat16* Bh = (FIRST ? g_Kt_hi : g_P_hi) + ((size_t)b * Ln + n0) * LD;
    const __nv_bfloat16* Bl = (FIRST ? g_Kt_lo : g_P_lo) + ((size_t)b * Ln + n0) * LD;
    float* D = (FIRST ? g_E : Dout) + (size_t)b * (FIRST ? Ln : Cn) * Ln;

    float* lmp = (float*)(smem + LM_OFF);
    if (FIRST && tid < 128)
        lmp[tid] = logf(mask[(size_t)b * Ln + n0 + tid] + 1e-6f);

    const int lane = tid & 31, wid = tid >> 5;
    const int wm = wid & 3, wn = wid >> 2;         // warp tile: 32 (m) x 64 (n)
    const int quad = lane >> 3, qj = lane & 7;
    const int a_row = (quad & 1) * 8 + qj;         // within m16
    const int a_kb  = (quad >> 1) * 16;            // byte offset within k16 row
    const int b_row = (quad >> 1) * 8 + qj;        // within n16
    const int b_kb  = (quad & 1) * 16;

    float acc[2][8][4];
#pragma unroll
    for (int fm = 0; fm < 2; fm++)
#pragma unroll
        for (int fn = 0; fn < 8; fn++)
#pragma unroll
            for (int e = 0; e < 4; e++) acc[fm][fn][e] = 0.0f;

    // ---- loader: one BK=32 slab into stage buffer `buf` ---------------------
    auto load_slab = [&](int buf, int it) {
        const uint32_t bb = sbase + buf * BUF_B;
        const int k0 = it * 32;
#pragma unroll
        for (int t = 0; t < 2; t++) {
            int f = t * 256 + tid;                 // 0..511
            int row = f >> 2, ch = f & 3;          // 128 rows x 4 x 16B
            uint32_t doff = SW((uint32_t)(row * ROWB + ch * 16));
            size_t soff = (size_t)row * LD + k0 + ch * 8;
            CP16(bb + OFF_AH + doff, Ah + soff);
            CP16(bb + OFF_AL + doff, Al + soff);
            CP16(bb + OFF_BH + doff, Bh + soff);
            CP16(bb + OFF_BL + doff, Bl + soff);
        }
        CP_COMMIT();
    };

    load_slab(0, 0);
    load_slab(1, 1);

    int buf = 0;
    for (int it = 0; it < NIT; it++) {
        if (it + 1 < NIT) { CP_WAIT1(); } else { CP_WAIT0(); }
        __syncthreads();   // slab `it` visible; all warps done with slab it-1
        if (it + 2 < NIT) {
            int nb = buf + 2; if (nb >= NSTAGE) nb -= NSTAGE;
            load_slab(nb, it + 2);
        }

        const uint32_t bb = sbase + buf * BUF_B;
#pragma unroll
        for (int ks = 0; ks < 2; ks++) {
            uint32_t ah[2][4], al[2][4];
#pragma unroll
            for (int fm = 0; fm < 2; fm++) {
                uint32_t r = SW((uint32_t)((wm * 32 + fm * 16 + a_row) * ROWB + ks * 32 + a_kb));
                ldsm_x4(bb + OFF_AH + r, ah[fm]);
                ldsm_x4(bb + OFF_AL + r, al[fm]);
            }
#pragma unroll
            for (int h = 0; h < 2; h++) {
                uint32_t bhr[4][2], blr[4][2];
#pragma unroll
                for (int g = 0; g < 2; g++) {
                    uint32_t r = SW((uint32_t)((wn * 64 + h * 32 + g * 16 + b_row) * ROWB + ks * 32 + b_kb));
                    uint32_t t4[4];
                    ldsm_x4(bb + OFF_BH + r, t4);
                    bhr[g * 2][0] = t4[0]; bhr[g * 2][1] = t4[1];
                    bhr[g * 2 + 1][0] = t4[2]; bhr[g * 2 + 1][1] = t4[3];
                    ldsm_x4(bb + OFF_BL + r, t4);
                    blr[g * 2][0] = t4[0]; blr[g * 2][1] = t4[1];
                    blr[g * 2 + 1][0] = t4[2]; blr[g * 2 + 1][1] = t4[3];
                }
#pragma unroll
                for (int fm = 0; fm < 2; fm++)
#pragma unroll
                    for (int fl = 0; fl < 4; fl++)
                        mma_bf16(acc[fm][h * 4 + fl], ah[fm], bhr[fl]);
#pragma unroll
                for (int fm = 0; fm < 2; fm++)
#pragma unroll
                    for (int fl = 0; fl < 4; fl++)
                        mma_bf16(acc[fm][h * 4 + fl], ah[fm], blr[fl]);
#pragma unroll
                for (int fm = 0; fm < 2; fm++)
#pragma unroll
                    for (int fl = 0; fl < 4; fl++)
                        mma_bf16(acc[fm][h * 4 + fl], al[fm], bhr[fl]);
            }
        }
        if (++buf == NSTAGE) buf = 0;
    }

    // ---- epilogue -----------------------------------------------------------
    const float scale = 0.04419417382415922f;      // 1/sqrt(512)
#pragma unroll
    for (int fm = 0; fm < 2; fm++)
#pragma unroll
        for (int fn = 0; fn < 8; fn++) {
            int r0 = m0 + wm * 32 + fm * 16 + (lane >> 2);
            int cl = wn * 64 + fn * 8 + (lane & 3) * 2;   // local col
            float v0 = acc[fm][fn][0], v1 = acc[fm][fn][1];
            float v2 = acc[fm][fn][2], v3 = acc[fm][fn][3];
            if (FIRST) {
                v0 = v0 * scale + lmp[cl];     v1 = v1 * scale + lmp[cl + 1];
                v2 = v2 * scale + lmp[cl];     v3 = v3 * scale + lmp[cl + 1];
            }
            *(float2*)&D[(size_t)r0 * Ln + n0 + cl]       = make_float2(v0, v1);
            *(float2*)&D[(size_t)(r0 + 8) * Ln + n0 + cl] = make_float2(v2, v3);
        }
}

// ---------------------------------------------------------------------------
// Convert + transpose Q,K: [b][C][L] fp32 -> [b][L][C] bf16 hi/lo
// ---------------------------------------------------------------------------
template <bool ISQ>
__global__ void convT_kernel(const float* __restrict__ X)
{
    __shared__ float tile[32][33];
    const int b = blockIdx.z, l0 = blockIdx.x * 32, c0 = blockIdx.y * 32;
    const int tx = threadIdx.x, ty = threadIdx.y;
#pragma unroll
    for (int r = 0; r < 32; r += 8)
        tile[ty + r][tx] = X[((size_t)b * Cn + c0 + ty + r) * Ln + l0 + tx];
    __syncthreads();
    __nv_bfloat16* Hi = ISQ ? g_Qt_hi : g_Kt_hi;
    __nv_bfloat16* Lo = ISQ ? g_Qt_lo : g_Kt_lo;
#pragma unroll
    for (int r = 0; r < 32; r += 8) {
        float v = tile[tx][ty + r];
        __nv_bfloat16 h, l; split_bf16(v, h, l);
        size_t idx = ((size_t)b * Ln + l0 + ty + r) * Cn + c0 + tx;
        Hi[idx] = h; Lo[idx] = l;
    }
}

// Convert V elementwise: fp32 -> bf16 hi/lo (same [b][C][L] layout)
__global__ void convV_kernel(const float* __restrict__ V)
{
    size_t idx = ((size_t)blockIdx.x * 256 + threadIdx.x) * 2;
    float2 v = *(const float2*)(V + idx);
    __nv_bfloat16 h0, l0, h1, l1;
    split_bf16(v.x, h0, l0); split_bf16(v.y, h1, l1);
    *(__nv_bfloat162*)(g_V_hi + idx) = __nv_bfloat162(h0, h1);
    *(__nv_bfloat162*)(g_V_lo + idx) = __nv_bfloat162(l0, l1);
}

// ---------------------------------------------------------------------------
// Row softmax over j + mask multiply; emits att as bf16 hi/lo [b][i][j]
// ---------------------------------------------------------------------------
__global__ __launch_bounds__(256) void softmax_mask_kernel(const float* __restrict__ mask)
{
    const int b = blockIdx.y, i = blockIdx.x;
    const size_t rowbase = ((size_t)b * Ln + i) * Ln;
    const float* row = g_E + rowbase;
    const float* mrow = mask + (size_t)b * Ln;
    const int tid = threadIdx.x;
    __shared__ float red[8];

    float v[16];
    float mx = -3.0e38f;
#pragma unroll
    for (int t = 0; t < 16; t++) { v[t] = row[t * 256 + tid]; mx = fmaxf(mx, v[t]); }
#pragma unroll
    for (int o = 16; o > 0; o >>= 1) mx = fmaxf(mx, __shfl_xor_sync(0xffffffffu, mx, o));
    if ((tid & 31) == 0) red[tid >> 5] = mx;
    __syncthreads();
    if (tid < 32) {
        float x = (tid < 8) ? red[tid] : -3.0e38f;
#pragma unroll
        for (int o = 4; o > 0; o >>= 1) x = fmaxf(x, __shfl_xor_sync(0xffffffffu, x, o));
        if (tid == 0) red[0] = x;
    }
    __syncthreads();
    mx = red[0];
    __syncthreads();

    float s = 0.0f;
#pragma unroll
    for (int t = 0; t < 16; t++) { v[t] = expf(v[t] - mx); s += v[t]; }
#pragma unroll
    for (int o = 16; o > 0; o >>= 1) s += __shfl_xor_sync(0xffffffffu, s, o);
    if ((tid & 31) == 0) red[tid >> 5] = s;
    __syncthreads();
    if (tid < 32) {
        float x = (tid < 8) ? red[tid] : 0.0f;
#pragma unroll
        for (int o = 4; o > 0; o >>= 1) x += __shfl_xor_sync(0xffffffffu, x, o);
        if (tid == 0) red[0] = x;
    }
    __syncthreads();
    const float inv = 1.0f / red[0];

#pragma unroll
    for (int t = 0; t < 16; t++) {
        const int j = t * 256 + tid;
        float val = v[t] * inv * mrow[j];
        __nv_bfloat16 h, l; split_bf16(val, h, l);
        g_P_hi[rowbase + j] = h;
        g_P_lo[rowbase + j] = l;
    }
}

// ---------------------------------------------------------------------------
// attT[b][j][i] = att[b][i][j]   (output-only transpose, hi+lo reconstruct)
// ---------------------------------------------------------------------------
__global__ void transP_kernel(float* __restrict__ AT)
{
    __shared__ float tile[32][33];
    const int b = blockIdx.z, j0 = blockIdx.x * 32, i0 = blockIdx.y * 32;
    const int tx = threadIdx.x, ty = threadIdx.y;
    float* Tb = AT + (size_t)b * Ln * Ln;
#pragma unroll
    for (int r = 0; r < 32; r += 8) {
        size_t idx = ((size_t)b * Ln + i0 + ty + r) * Ln + j0 + tx;
        tile[ty + r][tx] = __bfloat162float(g_P_hi[idx]) + __bfloat162float(g_P_lo[idx]);
    }
    __syncthreads();
#pragma unroll
    for (int r = 0; r < 32; r += 8)
        Tb[(size_t)(j0 + ty + r) * Ln + i0 + tx] = tile[tx][ty + r];
}

// ---------------------------------------------------------------------------
extern "C" void kernel_launch(void* const* d_in, const int* in_sizes, int n_in,
                              void* d_out, int out_size)
{
    const float* Q    = (const float*)d_in[0];
    const float* Kt   = (const float*)d_in[1];
    const float* V    = (const float*)d_in[2];
    const float* mask = (const float*)d_in[3];

    float* out  = (float*)d_out;                   // (B, C, L)
    float* attT = out + (size_t)Bn * Cn * Ln;      // (B, L, L)

    cudaFuncSetAttribute(mma_gemm_kernel<true>,
                         cudaFuncAttributeMaxDynamicSharedMemorySize, SMEM_BYTES);
    cudaFuncSetAttribute(mma_gemm_kernel<false>,
                         cudaFuncAttributeMaxDynamicSharedMemorySize, SMEM_BYTES);

    convT_kernel<true><<<dim3(Ln / 32, Cn / 32, Bn), dim3(32, 8)>>>(Q);
    convT_kernel<false><<<dim3(Ln / 32, Cn / 32, Bn), dim3(32, 8)>>>(Kt);
    convV_kernel<<<(int)(((size_t)Bn * Cn * Ln) / 512), 256>>>(V);

    mma_gemm_kernel<true><<<dim3(Ln / 128, Ln / 128, Bn), 256, SMEM_BYTES>>>(nullptr, mask);
    softmax_mask_kernel<<<dim3(Ln, Bn), 256>>>(mask);
    mma_gemm_kernel<false><<<dim3(Cn / 128, Ln / 128, Bn), 256, SMEM_BYTES>>>(out, nullptr);
    transP_kernel<<<dim3(Ln / 32, Ln / 32, Bn), dim3(32, 8)>>>(attT);
}

// round 6
// speedup vs baseline: 1.1663x; 1.1663x over previous
#include <cuda_runtime.h>
#include <cuda_bf16.h>
#include <math.h>
#include <stdint.h>

#define Bn 4
#define Cn 512
#define Ln 4096

// ---------------------------------------------------------------------------
// Scratch (static device globals; no allocation allowed)
// ---------------------------------------------------------------------------
__device__ float g_E[(size_t)Bn * Ln * Ln];                    // energy fp32 [b][i][j]
__device__ __nv_bfloat16 g_Qt_hi[(size_t)Bn * Ln * Cn];        // Q^T  [b][i][c]
__device__ __nv_bfloat16 g_Qt_lo[(size_t)Bn * Ln * Cn];
__device__ __nv_bfloat16 g_Kt_hi[(size_t)Bn * Ln * Cn];        // K^T  [b][j][c]
__device__ __nv_bfloat16 g_Kt_lo[(size_t)Bn * Ln * Cn];
__device__ __nv_bfloat16 g_V_hi[(size_t)Bn * Cn * Ln];         // V    [b][c][j]
__device__ __nv_bfloat16 g_V_lo[(size_t)Bn * Cn * Ln];
__device__ __nv_bfloat16 g_P_hi[(size_t)Bn * Ln * Ln];         // att  [b][i][j]
__device__ __nv_bfloat16 g_P_lo[(size_t)Bn * Ln * Ln];

// ---------------------------------------------------------------------------
// Base-ISA helpers (compute_103-safe: ldmatrix / mma.sync / cp.async)
// ---------------------------------------------------------------------------
__device__ __forceinline__ uint32_t smem_u32(const void* p) {
    uint32_t a;
    asm("{ .reg .u64 t; cvta.to.shared.u64 t, %1; cvt.u32.u64 %0, t; }" : "=r"(a) : "l"(p));
    return a;
}
__device__ __forceinline__ void ldsm_x4(uint32_t addr, uint32_t r[4]) {
    asm volatile("ldmatrix.sync.aligned.m8n8.x4.shared.b16 {%0,%1,%2,%3}, [%4];"
                 : "=r"(r[0]), "=r"(r[1]), "=r"(r[2]), "=r"(r[3]) : "r"(addr));
}
__device__ __forceinline__ void mma_bf16(float d[4], const uint32_t a[4], const uint32_t b[2]) {
    asm volatile("mma.sync.aligned.m16n8k16.row.col.f32.bf16.bf16.f32 "
                 "{%0,%1,%2,%3}, {%4,%5,%6,%7}, {%8,%9}, {%0,%1,%2,%3};"
                 : "+f"(d[0]), "+f"(d[1]), "+f"(d[2]), "+f"(d[3])
                 : "r"(a[0]), "r"(a[1]), "r"(a[2]), "r"(a[3]), "r"(b[0]), "r"(b[1]));
}
#define CP16(d, s) asm volatile("cp.async.cg.shared.global [%0], [%1], 16;" :: "r"(d), "l"(s))
#define CP_COMMIT() asm volatile("cp.async.commit_group;" ::: "memory")
#define CP_WAIT1()  asm volatile("cp.async.wait_group 1;" ::: "memory")
#define CP_WAIT0()  asm volatile("cp.async.wait_group 0;" ::: "memory")

__device__ __forceinline__ void split_bf16(float x, __nv_bfloat16& h, __nv_bfloat16& l) {
    h = __float2bfloat16(x);
    l = __float2bfloat16(x - __bfloat162float(h));
}

// ---------------------------------------------------------------------------
// smem geometry: 4 tiles (Ah, Al, Bh, Bl), 128 rows x 32 bf16 = 64 B rows,
// XOR-swizzled (conflict-free cp.async stores AND ldmatrix reads).
// Triple buffered: 3 x 32 KB = 96 KB; with regs capped at 128 -> 2 CTAs/SM.
// ---------------------------------------------------------------------------
#define SW(o) ((o) ^ (((o) >> 3) & 0x30))
#define ROWB 64
#define TILE_B (128 * ROWB)        // 8192
#define OFF_AH 0
#define OFF_AL (1 * TILE_B)
#define OFF_BH (2 * TILE_B)
#define OFF_BL (3 * TILE_B)
#define BUF_B  (4 * TILE_B)        // 32768
#define NSTAGE 3
#define LM_OFF (NSTAGE * BUF_B)    // 98304
#define SMEM_BYTES (NSTAGE * BUF_B + 512)

// ---------------------------------------------------------------------------
// bf16x3 tensor-core GEMM, 128x128 tile, BK=32, 256 threads, 3-stage pipeline.
// FIRST: E[i][j] = (Qt[i][:] . Kt[j][:]) * scale + logmask[j]    (K = 512)
// !FIRST: out[c][i] = V[c][:] . P[i][:]                          (K = 4096)
// ---------------------------------------------------------------------------
template <bool FIRST>
__global__ __launch_bounds__(256, 2) void mma_gemm_kernel(float* __restrict__ Dout,
                                                          const float* __restrict__ mask)
{
    constexpr int KTOT = FIRST ? Cn : Ln;
    constexpr int LD   = FIRST ? Cn : Ln;       // K-stride of A and B rows
    constexpr int NIT  = KTOT / 32;

    extern __shared__ char smem[];
    const uint32_t sbase = smem_u32(smem);
    const int tid = threadIdx.x;
    const int b = blockIdx.z;
    const int n0 = (FIRST ? blockIdx.x : blockIdx.y) * 128;
    const int m0 = (FIRST ? blockIdx.y : blockIdx.x) * 128;

    const __nv_bfloat16* Ah = (FIRST ? g_Qt_hi : g_V_hi) + ((size_t)b * (FIRST ? Ln : Cn) + m0) * LD;
    const __nv_bfloat16* Al = (FIRST ? g_Qt_lo : g_V_lo) + ((size_t)b * (FIRST ? Ln : Cn) + m0) * LD;
    const __nv_bfloat16* Bh = (FIRST ? g_Kt_hi : g_P_hi) + ((size_t)b * Ln + n0) * LD;
    const __nv_bfloat16* Bl = (FIRST ? g_Kt_lo : g_P_lo) + ((size_t)b * Ln + n0) * LD;
    float* D = (FIRST ? g_E : Dout) + (size_t)b * (FIRST ? Ln : Cn) * Ln;

    float* lmp = (float*)(smem + LM_OFF);
    if (FIRST && tid < 128)
        lmp[tid] = logf(mask[(size_t)b * Ln + n0 + tid] + 1e-6f);

    const int lane = tid & 31, wid = tid >> 5;
    const int wm = wid & 3, wn = wid >> 2;         // warp tile: 32 (m) x 64 (n)
    const int quad = lane >> 3, qj = lane & 7;
    const int a_row = (quad & 1) * 8 + qj;         // within m16
    const int a_kb  = (quad >> 1) * 16;            // byte offset within k16 row
    const int b_row = (quad >> 1) * 8 + qj;        // within n16
    const int b_kb  = (quad & 1) * 16;

    float acc[2][8][4];
#pragma unroll
    for (int fm = 0; fm < 2; fm++)
#pragma unroll
        for (int fn = 0; fn < 8; fn++)
#pragma unroll
            for (int e = 0; e < 4; e++) acc[fm][fn][e] = 0.0f;

    // ---- loader: one BK=32 slab into stage buffer `buf` ---------------------
    auto load_slab = [&](int buf, int it) {
        const uint32_t bb = sbase + buf * BUF_B;
        const int k0 = it * 32;
#pragma unroll
        for (int t = 0; t < 2; t++) {
            int f = t * 256 + tid;                 // 0..511
            int row = f >> 2, ch = f & 3;          // 128 rows x 4 x 16B
            uint32_t doff = SW((uint32_t)(row * ROWB + ch * 16));
            size_t soff = (size_t)row * LD + k0 + ch * 8;
            CP16(bb + OFF_AH + doff, Ah + soff);
            CP16(bb + OFF_AL + doff, Al + soff);
            CP16(bb + OFF_BH + doff, Bh + soff);
            CP16(bb + OFF_BL + doff, Bl + soff);
        }
        CP_COMMIT();
    };

    load_slab(0, 0);
    load_slab(1, 1);

    int buf = 0;
    for (int it = 0; it < NIT; it++) {
        if (it + 1 < NIT) { CP_WAIT1(); } else { CP_WAIT0(); }
        __syncthreads();   // slab `it` visible; all warps done with slab it-1
        if (it + 2 < NIT) {
            int nb = buf + 2; if (nb >= NSTAGE) nb -= NSTAGE;
            load_slab(nb, it + 2);
        }

        const uint32_t bb = sbase + buf * BUF_B;
#pragma unroll
        for (int ks = 0; ks < 2; ks++) {
            uint32_t ah[2][4], al[2][4];
#pragma unroll
            for (int fm = 0; fm < 2; fm++) {
                uint32_t r = SW((uint32_t)((wm * 32 + fm * 16 + a_row) * ROWB + ks * 32 + a_kb));
                ldsm_x4(bb + OFF_AH + r, ah[fm]);
                ldsm_x4(bb + OFF_AL + r, al[fm]);
            }
#pragma unroll
            for (int h = 0; h < 2; h++) {
                uint32_t bhr[4][2], blr[4][2];
#pragma unroll
                for (int g = 0; g < 2; g++) {
                    uint32_t r = SW((uint32_t)((wn * 64 + h * 32 + g * 16 + b_row) * ROWB + ks * 32 + b_kb));
                    uint32_t t4[4];
                    ldsm_x4(bb + OFF_BH + r, t4);
                    bhr[g * 2][0] = t4[0]; bhr[g * 2][1] = t4[1];
                    bhr[g * 2 + 1][0] = t4[2]; bhr[g * 2 + 1][1] = t4[3];
                    ldsm_x4(bb + OFF_BL + r, t4);
                    blr[g * 2][0] = t4[0]; blr[g * 2][1] = t4[1];
                    blr[g * 2 + 1][0] = t4[2]; blr[g * 2 + 1][1] = t4[3];
                }
#pragma unroll
                for (int fm = 0; fm < 2; fm++)
#pragma unroll
                    for (int fl = 0; fl < 4; fl++)
                        mma_bf16(acc[fm][h * 4 + fl], ah[fm], bhr[fl]);
#pragma unroll
                for (int fm = 0; fm < 2; fm++)
#pragma unroll
                    for (int fl = 0; fl < 4; fl++)
                        mma_bf16(acc[fm][h * 4 + fl], ah[fm], blr[fl]);
#pragma unroll
                for (int fm = 0; fm < 2; fm++)
#pragma unroll
                    for (int fl = 0; fl < 4; fl++)
                        mma_bf16(acc[fm][h * 4 + fl], al[fm], bhr[fl]);
            }
        }
        if (++buf == NSTAGE) buf = 0;
    }

    // ---- epilogue -----------------------------------------------------------
    const float scale = 0.04419417382415922f;      // 1/sqrt(512)
#pragma unroll
    for (int fm = 0; fm < 2; fm++)
#pragma unroll
        for (int fn = 0; fn < 8; fn++) {
            int r0 = m0 + wm * 32 + fm * 16 + (lane >> 2);
            int cl = wn * 64 + fn * 8 + (lane & 3) * 2;   // local col
            float v0 = acc[fm][fn][0], v1 = acc[fm][fn][1];
            float v2 = acc[fm][fn][2], v3 = acc[fm][fn][3];
            if (FIRST) {
                v0 = v0 * scale + lmp[cl];     v1 = v1 * scale + lmp[cl + 1];
                v2 = v2 * scale + lmp[cl];     v3 = v3 * scale + lmp[cl + 1];
            }
            *(float2*)&D[(size_t)r0 * Ln + n0 + cl]       = make_float2(v0, v1);
            *(float2*)&D[(size_t)(r0 + 8) * Ln + n0 + cl] = make_float2(v2, v3);
        }
}

// ---------------------------------------------------------------------------
// Convert + transpose Q,K: [b][C][L] fp32 -> [b][L][C] bf16 hi/lo
// ---------------------------------------------------------------------------
template <bool ISQ>
__global__ void convT_kernel(const float* __restrict__ X)
{
    __shared__ float tile[32][33];
    const int b = blockIdx.z, l0 = blockIdx.x * 32, c0 = blockIdx.y * 32;
    const int tx = threadIdx.x, ty = threadIdx.y;
#pragma unroll
    for (int r = 0; r < 32; r += 8)
        tile[ty + r][tx] = X[((size_t)b * Cn + c0 + ty + r) * Ln + l0 + tx];
    __syncthreads();
    __nv_bfloat16* Hi = ISQ ? g_Qt_hi : g_Kt_hi;
    __nv_bfloat16* Lo = ISQ ? g_Qt_lo : g_Kt_lo;
#pragma unroll
    for (int r = 0; r < 32; r += 8) {
        float v = tile[tx][ty + r];
        __nv_bfloat16 h, l; split_bf16(v, h, l);
        size_t idx = ((size_t)b * Ln + l0 + ty + r) * Cn + c0 + tx;
        Hi[idx] = h; Lo[idx] = l;
    }
}

// Convert V elementwise: fp32 -> bf16 hi/lo (same [b][C][L] layout)
__global__ void convV_kernel(const float* __restrict__ V)
{
    size_t idx = ((size_t)blockIdx.x * 256 + threadIdx.x) * 2;
    float2 v = *(const float2*)(V + idx);
    __nv_bfloat16 h0, l0, h1, l1;
    split_bf16(v.x, h0, l0); split_bf16(v.y, h1, l1);
    *(__nv_bfloat162*)(g_V_hi + idx) = __nv_bfloat162(h0, h1);
    *(__nv_bfloat162*)(g_V_lo + idx) = __nv_bfloat162(l0, l1);
}

// ---------------------------------------------------------------------------
// Row softmax over j + mask multiply; emits att as bf16 hi/lo [b][i][j]
// ---------------------------------------------------------------------------
__global__ __launch_bounds__(256) void softmax_mask_kernel(const float* __restrict__ mask)
{
    const int b = blockIdx.y, i = blockIdx.x;
    const size_t rowbase = ((size_t)b * Ln + i) * Ln;
    const float* row = g_E + rowbase;
    const float* mrow = mask + (size_t)b * Ln;
    const int tid = threadIdx.x;
    __shared__ float red[8];

    float v[16];
    float mx = -3.0e38f;
#pragma unroll
    for (int t = 0; t < 16; t++) { v[t] = row[t * 256 + tid]; mx = fmaxf(mx, v[t]); }
#pragma unroll
    for (int o = 16; o > 0; o >>= 1) mx = fmaxf(mx, __shfl_xor_sync(0xffffffffu, mx, o));
    if ((tid & 31) == 0) red[tid >> 5] = mx;
    __syncthreads();
    if (tid < 32) {
        float x = (tid < 8) ? red[tid] : -3.0e38f;
#pragma unroll
        for (int o = 4; o > 0; o >>= 1) x = fmaxf(x, __shfl_xor_sync(0xffffffffu, x, o));
        if (tid == 0) red[0] = x;
    }
    __syncthreads();
    mx = red[0];
    __syncthreads();

    float s = 0.0f;
#pragma unroll
    for (int t = 0; t < 16; t++) { v[t] = expf(v[t] - mx); s += v[t]; }
#pragma unroll
    for (int o = 16; o > 0; o >>= 1) s += __shfl_xor_sync(0xffffffffu, s, o);
    if ((tid & 31) == 0) red[tid >> 5] = s;
    __syncthreads();
    if (tid < 32) {
        float x = (tid < 8) ? red[tid] : 0.0f;
#pragma unroll
        for (int o = 4; o > 0; o >>= 1) x += __shfl_xor_sync(0xffffffffu, x, o);
        if (tid == 0) red[0] = x;
    }
    __syncthreads();
    const float inv = 1.0f / red[0];

#pragma unroll
    for (int t = 0; t < 16; t++) {
        const int j = t * 256 + tid;
        float val = v[t] * inv * mrow[j];
        __nv_bfloat16 h, l; split_bf16(val, h, l);
        g_P_hi[rowbase + j] = h;
        g_P_lo[rowbase + j] = l;
    }
}

// ---------------------------------------------------------------------------
// attT[b][j][i] = att[b][i][j]   (output-only transpose, hi+lo reconstruct)
// ---------------------------------------------------------------------------
__global__ void transP_kernel(float* __restrict__ AT)
{
    __shared__ float tile[32][33];
    const int b = blockIdx.z, j0 = blockIdx.x * 32, i0 = blockIdx.y * 32;
    const int tx = threadIdx.x, ty = threadIdx.y;
    float* Tb = AT + (size_t)b * Ln * Ln;
#pragma unroll
    for (int r = 0; r < 32; r += 8) {
        size_t idx = ((size_t)b * Ln + i0 + ty + r) * Ln + j0 + tx;
        tile[ty + r][tx] = __bfloat162float(g_P_hi[idx]) + __bfloat162float(g_P_lo[idx]);
    }
    __syncthreads();
#pragma unroll
    for (int r = 0; r < 32; r += 8)
        Tb[(size_t)(j0 + ty + r) * Ln + i0 + tx] = tile[tx][ty + r];
}

// ---------------------------------------------------------------------------
extern "C" void kernel_launch(void* const* d_in, const int* in_sizes, int n_in,
                              void* d_out, int out_size)
{
    const float* Q    = (const float*)d_in[0];
    const float* Kt   = (const float*)d_in[1];
    const float* V    = (const float*)d_in[2];
    const float* mask = (const float*)d_in[3];

    float* out  = (float*)d_out;                   // (B, C, L)
    float* attT = out + (size_t)Bn * Cn * Ln;      // (B, L, L)

    cudaFuncSetAttribute(mma_gemm_kernel<true>,
                         cudaFuncAttributeMaxDynamicSharedMemorySize, SMEM_BYTES);
    cudaFuncSetAttribute(mma_gemm_kernel<false>,
                         cudaFuncAttributeMaxDynamicSharedMemorySize, SMEM_BYTES);

    convT_kernel<true><<<dim3(Ln / 32, Cn / 32, Bn), dim3(32, 8)>>>(Q);
    convT_kernel<false><<<dim3(Ln / 32, Cn / 32, Bn), dim3(32, 8)>>>(Kt);
    convV_kernel<<<(int)(((size_t)Bn * Cn * Ln) / 512), 256>>>(V);

    mma_gemm_kernel<true><<<dim3(Ln / 128, Ln / 128, Bn), 256, SMEM_BYTES>>>(nullptr, mask);
    softmax_mask_kernel<<<dim3(Ln, Bn), 256>>>(mask);
    mma_gemm_kernel<false><<<dim3(Cn / 128, Ln / 128, Bn), 256, SMEM_BYTES>>>(out, nullptr);
    transP_kernel<<<dim3(Ln / 32, Ln / 32, Bn), dim3(32, 8)>>>(attT);
}

// round 8
// speedup vs baseline: 1.1719x; 1.0048x over previous
#include <cuda_runtime.h>
#include <cuda_bf16.h>
#include <math.h>
#include <stdint.h>

#define Bn 4
#define Cn 512
#define Ln 4096

// ---------------------------------------------------------------------------
// Scratch (static device globals; no allocation allowed)
// ---------------------------------------------------------------------------
__device__ float g_E[(size_t)Bn * Ln * Ln];                    // unnormalized exp [b][i][j]
__device__ float g_S[(size_t)Bn * Ln];                         // row sums of exp
__device__ __nv_bfloat16 g_Qt_hi[(size_t)Bn * Ln * Cn];        // Q^T  [b][i][c]
__device__ __nv_bfloat16 g_Qt_lo[(size_t)Bn * Ln * Cn];
__device__ __nv_bfloat16 g_Kt_hi[(size_t)Bn * Ln * Cn];        // K^T  [b][j][c]
__device__ __nv_bfloat16 g_Kt_lo[(size_t)Bn * Ln * Cn];
__device__ __nv_bfloat16 g_V_hi[(size_t)Bn * Cn * Ln];         // V    [b][c][j]
__device__ __nv_bfloat16 g_V_lo[(size_t)Bn * Cn * Ln];
__device__ __nv_bfloat16 g_P_hi[(size_t)Bn * Ln * Ln];         // att  [b][i][j]
__device__ __nv_bfloat16 g_P_lo[(size_t)Bn * Ln * Ln];

// ---------------------------------------------------------------------------
// Base-ISA helpers (compute_103-safe: ldmatrix / mma.sync / cp.async)
// ---------------------------------------------------------------------------
__device__ __forceinline__ uint32_t smem_u32(const void* p) {
    uint32_t a;
    asm("{ .reg .u64 t; cvta.to.shared.u64 t, %1; cvt.u32.u64 %0, t; }" : "=r"(a) : "l"(p));
    return a;
}
__device__ __forceinline__ void ldsm_x4(uint32_t addr, uint32_t r[4]) {
    asm volatile("ldmatrix.sync.aligned.m8n8.x4.shared.b16 {%0,%1,%2,%3}, [%4];"
                 : "=r"(r[0]), "=r"(r[1]), "=r"(r[2]), "=r"(r[3]) : "r"(addr));
}
__device__ __forceinline__ void mma_bf16(float d[4], const uint32_t a[4], const uint32_t b[2]) {
    asm volatile("mma.sync.aligned.m16n8k16.row.col.f32.bf16.bf16.f32 "
                 "{%0,%1,%2,%3}, {%4,%5,%6,%7}, {%8,%9}, {%0,%1,%2,%3};"
                 : "+f"(d[0]), "+f"(d[1]), "+f"(d[2]), "+f"(d[3])
                 : "r"(a[0]), "r"(a[1]), "r"(a[2]), "r"(a[3]), "r"(b[0]), "r"(b[1]));
}
#define CP16(d, s) asm volatile("cp.async.cg.shared.global [%0], [%1], 16;" :: "r"(d), "l"(s))
#define CP_COMMIT() asm volatile("cp.async.commit_group;" ::: "memory")
#define CP_WAIT1()  asm volatile("cp.async.wait_group 1;" ::: "memory")
#define CP_WAIT0()  asm volatile("cp.async.wait_group 0;" ::: "memory")

__device__ __forceinline__ void split_bf16(float x, __nv_bfloat16& h, __nv_bfloat16& l) {
    h = __float2bfloat16(x);
    l = __float2bfloat16(x - __bfloat162float(h));
}

// ---------------------------------------------------------------------------
// smem geometry: 4 tiles (Ah, Al, Bh, Bl), 128 rows x 32 bf16 = 64 B rows,
// XOR-swizzled. Triple buffered; regs capped at 128 -> 2 CTAs/SM.
// ---------------------------------------------------------------------------
#define SW(o) ((o) ^ (((o) >> 3) & 0x30))
#define ROWB 64
#define TILE_B (128 * ROWB)        // 8192
#define OFF_AH 0
#define OFF_AL (1 * TILE_B)
#define OFF_BH (2 * TILE_B)
#define OFF_BL (3 * TILE_B)
#define BUF_B  (4 * TILE_B)        // 32768
#define NSTAGE 3
#define LM_OFF (NSTAGE * BUF_B)    // 98304
#define SMEM_BYTES (NSTAGE * BUF_B + 512)

// ---------------------------------------------------------------------------
// bf16x3 tensor-core GEMM, 128x128 tile, BK=32, 256 threads, 3-stage pipeline.
// Main loop identical to the 1193us winner.
// FIRST: g_E[i][j] = exp(QtK*scale)*(mask+1e-6); row sums atomically -> g_S
// !FIRST: out[c][i] = V[c][:] . P[i][:]
// ---------------------------------------------------------------------------
template <bool FIRST>
__global__ __launch_bounds__(256, 2) void mma_gemm_kernel(float* __restrict__ Dout,
                                                          const float* __restrict__ mask)
{
    constexpr int KTOT = FIRST ? Cn : Ln;
    constexpr int LD   = FIRST ? Cn : Ln;
    constexpr int NIT  = KTOT / 32;

    extern __shared__ char smem[];
    const uint32_t sbase = smem_u32(smem);
    const int tid = threadIdx.x;
    const int b = blockIdx.z;
    const int n0 = (FIRST ? blockIdx.x : blockIdx.y) * 128;
    const int m0 = (FIRST ? blockIdx.y : blockIdx.x) * 128;

    const __nv_bfloat16* Ah = (FIRST ? g_Qt_hi : g_V_hi) + ((size_t)b * (FIRST ? Ln : Cn) + m0) * LD;
    const __nv_bfloat16* Al = (FIRST ? g_Qt_lo : g_V_lo) + ((size_t)b * (FIRST ? Ln : Cn) + m0) * LD;
    const __nv_bfloat16* Bh = (FIRST ? g_Kt_hi : g_P_hi) + ((size_t)b * Ln + n0) * LD;
    const __nv_bfloat16* Bl = (FIRST ? g_Kt_lo : g_P_lo) + ((size_t)b * Ln + n0) * LD;
    float* D = (FIRST ? g_E : Dout) + (size_t)b * (FIRST ? Ln : Cn) * Ln;

    float* lmp = (float*)(smem + LM_OFF);
    if (FIRST && tid < 128)
        lmp[tid] = mask[(size_t)b * Ln + n0 + tid] + 1e-6f;   // mask epsilon (not log)

    const int lane = tid & 31, wid = tid >> 5;
    const int wm = wid & 3, wn = wid >> 2;
    const int quad = lane >> 3, qj = lane & 7;
    const int a_row = (quad & 1) * 8 + qj;
    const int a_kb  = (quad >> 1) * 16;
    const int b_row = (quad >> 1) * 8 + qj;
    const int b_kb  = (quad & 1) * 16;

    float acc[2][8][4];
#pragma unroll
    for (int fm = 0; fm < 2; fm++)
#pragma unroll
        for (int fn = 0; fn < 8; fn++)
#pragma unroll
            for (int e = 0; e < 4; e++) acc[fm][fn][e] = 0.0f;

    auto load_slab = [&](int buf, int it) {
        const uint32_t bb = sbase + buf * BUF_B;
        const int k0 = it * 32;
#pragma unroll
        for (int t = 0; t < 2; t++) {
            int f = t * 256 + tid;
            int row = f >> 2, ch = f & 3;
            uint32_t doff = SW((uint32_t)(row * ROWB + ch * 16));
            size_t soff = (size_t)row * LD + k0 + ch * 8;
            CP16(bb + OFF_AH + doff, Ah + soff);
            CP16(bb + OFF_AL + doff, Al + soff);
            CP16(bb + OFF_BH + doff, Bh + soff);
            CP16(bb + OFF_BL + doff, Bl + soff);
        }
        CP_COMMIT();
    };

    load_slab(0, 0);
    load_slab(1, 1);

    int buf = 0;
    for (int it = 0; it < NIT; it++) {
        if (it + 1 < NIT) { CP_WAIT1(); } else { CP_WAIT0(); }
        __syncthreads();
        if (it + 2 < NIT) {
            int nb = buf + 2; if (nb >= NSTAGE) nb -= NSTAGE;
            load_slab(nb, it + 2);
        }

        const uint32_t bb = sbase + buf * BUF_B;
#pragma unroll
        for (int ks = 0; ks < 2; ks++) {
            uint32_t ah[2][4], al[2][4];
#pragma unroll
            for (int fm = 0; fm < 2; fm++) {
                uint32_t r = SW((uint32_t)((wm * 32 + fm * 16 + a_row) * ROWB + ks * 32 + a_kb));
                ldsm_x4(bb + OFF_AH + r, ah[fm]);
                ldsm_x4(bb + OFF_AL + r, al[fm]);
            }
#pragma unroll
            for (int h = 0; h < 2; h++) {
                uint32_t bhr[4][2], blr[4][2];
#pragma unroll
                for (int g = 0; g < 2; g++) {
                    uint32_t r = SW((uint32_t)((wn * 64 + h * 32 + g * 16 + b_row) * ROWB + ks * 32 + b_kb));
                    uint32_t t4[4];
                    ldsm_x4(bb + OFF_BH + r, t4);
                    bhr[g * 2][0] = t4[0]; bhr[g * 2][1] = t4[1];
                    bhr[g * 2 + 1][0] = t4[2]; bhr[g * 2 + 1][1] = t4[3];
                    ldsm_x4(bb + OFF_BL + r, t4);
                    blr[g * 2][0] = t4[0]; blr[g * 2][1] = t4[1];
                    blr[g * 2 + 1][0] = t4[2]; blr[g * 2 + 1][1] = t4[3];
                }
#pragma unroll
                for (int fm = 0; fm < 2; fm++)
#pragma unroll
                    for (int fl = 0; fl < 4; fl++)
                        mma_bf16(acc[fm][h * 4 + fl], ah[fm], bhr[fl]);
#pragma unroll
                for (int fm = 0; fm < 2; fm++)
#pragma unroll
                    for (int fl = 0; fl < 4; fl++)
                        mma_bf16(acc[fm][h * 4 + fl], ah[fm], blr[fl]);
#pragma unroll
                for (int fm = 0; fm < 2; fm++)
#pragma unroll
                    for (int fl = 0; fl < 4; fl++)
                        mma_bf16(acc[fm][h * 4 + fl], al[fm], bhr[fl]);
            }
        }
        if (++buf == NSTAGE) buf = 0;
    }

    const float scale = 0.04419417382415922f;      // 1/sqrt(512)
    if (FIRST) {
        float* S = g_S + (size_t)b * Ln;
#pragma unroll
        for (int fm = 0; fm < 2; fm++) {
            const int r0 = m0 + wm * 32 + fm * 16 + (lane >> 2);
            float rs0 = 0.0f, rs1 = 0.0f;
#pragma unroll
            for (int fn = 0; fn < 8; fn++) {
                int cl = wn * 64 + fn * 8 + (lane & 3) * 2;
                float me0 = lmp[cl], me1 = lmp[cl + 1];
                float v0 = expf(acc[fm][fn][0] * scale) * me0;
                float v1 = expf(acc[fm][fn][1] * scale) * me1;
                float v2 = expf(acc[fm][fn][2] * scale) * me0;
                float v3 = expf(acc[fm][fn][3] * scale) * me1;
                rs0 += v0 + v1;
                rs1 += v2 + v3;
                *(float2*)&D[(size_t)r0 * Ln + n0 + cl]       = make_float2(v0, v1);
                *(float2*)&D[(size_t)(r0 + 8) * Ln + n0 + cl] = make_float2(v2, v3);
            }
            // reduce across the 4 lanes of the quad (same rows, different cols)
            rs0 += __shfl_xor_sync(0xffffffffu, rs0, 1);
            rs0 += __shfl_xor_sync(0xffffffffu, rs0, 2);
            rs1 += __shfl_xor_sync(0xffffffffu, rs1, 1);
            rs1 += __shfl_xor_sync(0xffffffffu, rs1, 2);
            if ((lane & 3) == 0) {
                atomicAdd(&S[r0], rs0);
                atomicAdd(&S[r0 + 8], rs1);
            }
        }
    } else {
#pragma unroll
        for (int fm = 0; fm < 2; fm++)
#pragma unroll
            for (int fn = 0; fn < 8; fn++) {
                int r0 = m0 + wm * 32 + fm * 16 + (lane >> 2);
                int cl = wn * 64 + fn * 8 + (lane & 3) * 2;
                *(float2*)&D[(size_t)r0 * Ln + n0 + cl]       = make_float2(acc[fm][fn][0], acc[fm][fn][1]);
                *(float2*)&D[(size_t)(r0 + 8) * Ln + n0 + cl] = make_float2(acc[fm][fn][2], acc[fm][fn][3]);
            }
    }
}

// ---------------------------------------------------------------------------
// Zero the row-sum accumulators (graph-replay safe)
// ---------------------------------------------------------------------------
__global__ void zeroS_kernel()
{
    g_S[blockIdx.x * 256 + threadIdx.x] = 0.0f;
}

// ---------------------------------------------------------------------------
// Convert + transpose Q,K: [b][C][L] fp32 -> [b][L][C] bf16 hi/lo
// ---------------------------------------------------------------------------
template <bool ISQ>
__global__ void convT_kernel(const float* __restrict__ X)
{
    __shared__ float tile[32][33];
    const int b = blockIdx.z, l0 = blockIdx.x * 32, c0 = blockIdx.y * 32;
    const int tx = threadIdx.x, ty = threadIdx.y;
#pragma unroll
    for (int r = 0; r < 32; r += 8)
        tile[ty + r][tx] = X[((size_t)b * Cn + c0 + ty + r) * Ln + l0 + tx];
    __syncthreads();
    __nv_bfloat16* Hi = ISQ ? g_Qt_hi : g_Kt_hi;
    __nv_bfloat16* Lo = ISQ ? g_Qt_lo : g_Kt_lo;
#pragma unroll
    for (int r = 0; r < 32; r += 8) {
        float v = tile[tx][ty + r];
        __nv_bfloat16 h, l; split_bf16(v, h, l);
        size_t idx = ((size_t)b * Ln + l0 + ty + r) * Cn + c0 + tx;
        Hi[idx] = h; Lo[idx] = l;
    }
}

// Convert V elementwise: fp32 -> bf16 hi/lo (same [b][C][L] layout)
__global__ void convV_kernel(const float* __restrict__ V)
{
    size_t idx = ((size_t)blockIdx.x * 256 + threadIdx.x) * 2;
    float2 v = *(const float2*)(V + idx);
    __nv_bfloat16 h0, l0, h1, l1;
    split_bf16(v.x, h0, l0); split_bf16(v.y, h1, l1);
    *(__nv_bfloat162*)(g_V_hi + idx) = __nv_bfloat162(h0, h1);
    *(__nv_bfloat162*)(g_V_lo + idx) = __nv_bfloat162(l0, l1);
}

// ---------------------------------------------------------------------------
// scaleT: one pass produces BOTH GEMM2's B operand and the attention output.
//   p = g_E[i][j] * (1/g_S[i]) * mask[j]
//   g_P_hi/lo[b][i][j] = split(p);  AT[b][j][i] = p  (64x64 smem transpose)
// ---------------------------------------------------------------------------
__global__ __launch_bounds__(256) void scaleT_kernel(float* __restrict__ AT,
                                                     const float* __restrict__ mask)
{
    __shared__ float tile[64][65];
    __shared__ float sinv[64], smask[64];
    const int b = blockIdx.z, j0 = blockIdx.x * 64, i0 = blockIdx.y * 64;
    const int t = threadIdx.x;
    const int r = t >> 2;            // 0..63 (row i0+r)
    const int seg = t & 3;           // 16 contiguous j's each

    if (t < 64)       sinv[t] = 1.0f / g_S[(size_t)b * Ln + i0 + t];
    else if (t < 128) smask[t - 64] = mask[(size_t)b * Ln + j0 + (t - 64)];
    __syncthreads();

    float v[16];
    {
        const float* src = g_E + ((size_t)b * Ln + i0 + r) * Ln + j0 + seg * 16;
#pragma unroll
        for (int q = 0; q < 4; q++)
            *(float4*)&v[q * 4] = *(const float4*)&src[q * 4];
    }
    const float inv = sinv[r];

    uint32_t ph[8], pl[8];
#pragma unroll
    for (int k = 0; k < 8; k++) {
        float a = v[2 * k]     * inv * smask[seg * 16 + 2 * k];
        float c = v[2 * k + 1] * inv * smask[seg * 16 + 2 * k + 1];
        tile[r][seg * 16 + 2 * k]     = a;
        tile[r][seg * 16 + 2 * k + 1] = c;
        __nv_bfloat16 ha, la, hc, lc;
        split_bf16(a, ha, la);
        split_bf16(c, hc, lc);
        __nv_bfloat162 hp(ha, hc), lp(la, lc);
        ph[k] = *(uint32_t*)&hp;
        pl[k] = *(uint32_t*)&lp;
    }
    {
        size_t rowbase = ((size_t)b * Ln + i0 + r) * Ln + j0 + seg * 16;
        *(uint4*)&g_P_hi[rowbase]     = make_uint4(ph[0], ph[1], ph[2], ph[3]);
        *(uint4*)&g_P_hi[rowbase + 8] = make_uint4(ph[4], ph[5], ph[6], ph[7]);
        *(uint4*)&g_P_lo[rowbase]     = make_uint4(pl[0], pl[1], pl[2], pl[3]);
        *(uint4*)&g_P_lo[rowbase + 8] = make_uint4(pl[4], pl[5], pl[6], pl[7]);
    }
    __syncthreads();

    float o[16];
#pragma unroll
    for (int k = 0; k < 16; k++)
        o[k] = tile[seg * 16 + k][r];
    float* dst = AT + ((size_t)b * Ln + j0 + r) * Ln + i0 + seg * 16;
#pragma unroll
    for (int q = 0; q < 4; q++)
        *(float4*)&dst[q * 4] = *(float4*)&o[q * 4];
}

// ---------------------------------------------------------------------------
extern "C" void kernel_launch(void* const* d_in, const int* in_sizes, int n_in,
                              void* d_out, int out_size)
{
    const float* Q    = (const float*)d_in[0];
    const float* Kt   = (const float*)d_in[1];
    const float* V    = (const float*)d_in[2];
    const float* mask = (const float*)d_in[3];

    float* out  = (float*)d_out;                   // (B, C, L)
    float* attT = out + (size_t)Bn * Cn * Ln;      // (B, L, L)

    cudaFuncSetAttribute(mma_gemm_kernel<true>,
                         cudaFuncAttributeMaxDynamicSharedMemorySize, SMEM_BYTES);
    cudaFuncSetAttribute(mma_gemm_kernel<false>,
                         cudaFuncAttributeMaxDynamicSharedMemorySize, SMEM_BYTES);

    zeroS_kernel<<<(Bn * Ln) / 256, 256>>>();
    convT_kernel<true><<<dim3(Ln / 32, Cn / 32, Bn), dim3(32, 8)>>>(Q);
    convT_kernel<false><<<dim3(Ln / 32, Cn / 32, Bn), dim3(32, 8)>>>(Kt);
    convV_kernel<<<(int)(((size_t)Bn * Cn * Ln) / 512), 256>>>(V);

    mma_gemm_kernel<true><<<dim3(Ln / 128, Ln / 128, Bn), 256, SMEM_BYTES>>>(nullptr, mask);
    scaleT_kernel<<<dim3(Ln / 64, Ln / 64, Bn), 256>>>(attT, mask);
    mma_gemm_kernel<false><<<dim3(Cn / 128, Ln / 128, Bn), 256, SMEM_BYTES>>>(out, nullptr);
}

// round 9
// speedup vs baseline: 1.1818x; 1.0085x over previous
#include <cuda_runtime.h>
#include <cuda_bf16.h>
#include <math.h>
#include <stdint.h>

#define Bn 4
#define Cn 512
#define Ln 4096

// ---------------------------------------------------------------------------
// Scratch (static device globals; no allocation allowed)
// ---------------------------------------------------------------------------
__device__ float g_S[(size_t)Bn * Ln];                         // row sums of exp_un
__device__ __nv_bfloat16 g_Qt_hi[(size_t)Bn * Ln * Cn];        // Q^T  [b][i][c]
__device__ __nv_bfloat16 g_Qt_lo[(size_t)Bn * Ln * Cn];
__device__ __nv_bfloat16 g_Kt_hi[(size_t)Bn * Ln * Cn];        // K^T  [b][j][c]
__device__ __nv_bfloat16 g_Kt_lo[(size_t)Bn * Ln * Cn];
__device__ __nv_bfloat16 g_V_hi[(size_t)Bn * Cn * Ln];         // V*mask [b][c][j]
__device__ __nv_bfloat16 g_V_lo[(size_t)Bn * Cn * Ln];
__device__ __nv_bfloat16 g_P_hi[(size_t)Bn * Ln * Ln];         // exp_un [b][i][j]
__device__ __nv_bfloat16 g_P_lo[(size_t)Bn * Ln * Ln];

// ---------------------------------------------------------------------------
// Base-ISA helpers (compute_103-safe: ldmatrix / mma.sync / cp.async)
// ---------------------------------------------------------------------------
__device__ __forceinline__ uint32_t smem_u32(const void* p) {
    uint32_t a;
    asm("{ .reg .u64 t; cvta.to.shared.u64 t, %1; cvt.u32.u64 %0, t; }" : "=r"(a) : "l"(p));
    return a;
}
__device__ __forceinline__ void ldsm_x4(uint32_t addr, uint32_t r[4]) {
    asm volatile("ldmatrix.sync.aligned.m8n8.x4.shared.b16 {%0,%1,%2,%3}, [%4];"
                 : "=r"(r[0]), "=r"(r[1]), "=r"(r[2]), "=r"(r[3]) : "r"(addr));
}
__device__ __forceinline__ void mma_bf16(float d[4], const uint32_t a[4], const uint32_t b[2]) {
    asm volatile("mma.sync.aligned.m16n8k16.row.col.f32.bf16.bf16.f32 "
                 "{%0,%1,%2,%3}, {%4,%5,%6,%7}, {%8,%9}, {%0,%1,%2,%3};"
                 : "+f"(d[0]), "+f"(d[1]), "+f"(d[2]), "+f"(d[3])
                 : "r"(a[0]), "r"(a[1]), "r"(a[2]), "r"(a[3]), "r"(b[0]), "r"(b[1]));
}
#define CP16(d, s) asm volatile("cp.async.cg.shared.global [%0], [%1], 16;" :: "r"(d), "l"(s))
#define CP_COMMIT() asm volatile("cp.async.commit_group;" ::: "memory")
#define CP_WAIT1()  asm volatile("cp.async.wait_group 1;" ::: "memory")
#define CP_WAIT0()  asm volatile("cp.async.wait_group 0;" ::: "memory")

__device__ __forceinline__ void split_bf16(float x, __nv_bfloat16& h, __nv_bfloat16& l) {
    h = __float2bfloat16(x);
    l = __float2bfloat16(x - __bfloat162float(h));
}

// ---------------------------------------------------------------------------
// smem geometry: 4 tiles (Ah, Al, Bh, Bl), 128 rows x 32 bf16 = 64 B rows,
// XOR-swizzled. Triple buffered; regs capped at 128 -> 2 CTAs/SM.
// ---------------------------------------------------------------------------
#define SW(o) ((o) ^ (((o) >> 3) & 0x30))
#define ROWB 64
#define TILE_B (128 * ROWB)        // 8192
#define OFF_AH 0
#define OFF_AL (1 * TILE_B)
#define OFF_BH (2 * TILE_B)
#define OFF_BL (3 * TILE_B)
#define BUF_B  (4 * TILE_B)        // 32768
#define NSTAGE 3
#define LM_OFF (NSTAGE * BUF_B)    // 98304
#define SMEM_BYTES (NSTAGE * BUF_B + 512)

// ---------------------------------------------------------------------------
// bf16x3 tensor-core GEMM, 128x128 tile, BK=32, 256 threads, 3-stage pipeline.
// Main loop identical to the proven 74%-tensor configuration.
// FIRST: P_un[i][j] = exp(QtK*scale)*(mask+1e-6) as bf16 hi/lo; row sums -> g_S
// !FIRST: out[c][i] = (Σ_j V'[c][j]·P_un[i][j]) / S_i
// ---------------------------------------------------------------------------
template <bool FIRST>
__global__ __launch_bounds__(256, 2) void mma_gemm_kernel(float* __restrict__ Dout,
                                                          const float* __restrict__ mask)
{
    constexpr int KTOT = FIRST ? Cn : Ln;
    constexpr int LD   = FIRST ? Cn : Ln;
    constexpr int NIT  = KTOT / 32;

    extern __shared__ char smem[];
    const uint32_t sbase = smem_u32(smem);
    const int tid = threadIdx.x;
    const int b = blockIdx.z;
    const int n0 = (FIRST ? blockIdx.x : blockIdx.y) * 128;
    const int m0 = (FIRST ? blockIdx.y : blockIdx.x) * 128;

    const __nv_bfloat16* Ah = (FIRST ? g_Qt_hi : g_V_hi) + ((size_t)b * (FIRST ? Ln : Cn) + m0) * LD;
    const __nv_bfloat16* Al = (FIRST ? g_Qt_lo : g_V_lo) + ((size_t)b * (FIRST ? Ln : Cn) + m0) * LD;
    const __nv_bfloat16* Bh = (FIRST ? g_Kt_hi : g_P_hi) + ((size_t)b * Ln + n0) * LD;
    const __nv_bfloat16* Bl = (FIRST ? g_Kt_lo : g_P_lo) + ((size_t)b * Ln + n0) * LD;

    float* lmp = (float*)(smem + LM_OFF);
    if (FIRST) {
        if (tid < 128) lmp[tid] = mask[(size_t)b * Ln + n0 + tid] + 1e-6f;
    } else {
        if (tid < 128) lmp[tid] = 1.0f / g_S[(size_t)b * Ln + n0 + tid];
    }

    const int lane = tid & 31, wid = tid >> 5;
    const int wm = wid & 3, wn = wid >> 2;
    const int quad = lane >> 3, qj = lane & 7;
    const int a_row = (quad & 1) * 8 + qj;
    const int a_kb  = (quad >> 1) * 16;
    const int b_row = (quad >> 1) * 8 + qj;
    const int b_kb  = (quad & 1) * 16;

    float acc[2][8][4];
#pragma unroll
    for (int fm = 0; fm < 2; fm++)
#pragma unroll
        for (int fn = 0; fn < 8; fn++)
#pragma unroll
            for (int e = 0; e < 4; e++) acc[fm][fn][e] = 0.0f;

    auto load_slab = [&](int buf, int it) {
        const uint32_t bb = sbase + buf * BUF_B;
        const int k0 = it * 32;
#pragma unroll
        for (int t = 0; t < 2; t++) {
            int f = t * 256 + tid;
            int row = f >> 2, ch = f & 3;
            uint32_t doff = SW((uint32_t)(row * ROWB + ch * 16));
            size_t soff = (size_t)row * LD + k0 + ch * 8;
            CP16(bb + OFF_AH + doff, Ah + soff);
            CP16(bb + OFF_AL + doff, Al + soff);
            CP16(bb + OFF_BH + doff, Bh + soff);
            CP16(bb + OFF_BL + doff, Bl + soff);
        }
        CP_COMMIT();
    };

    load_slab(0, 0);
    load_slab(1, 1);

    int buf = 0;
    for (int it = 0; it < NIT; it++) {
        if (it + 1 < NIT) { CP_WAIT1(); } else { CP_WAIT0(); }
        __syncthreads();
        if (it + 2 < NIT) {
            int nb = buf + 2; if (nb >= NSTAGE) nb -= NSTAGE;
            load_slab(nb, it + 2);
        }

        const uint32_t bb = sbase + buf * BUF_B;
#pragma unroll
        for (int ks = 0; ks < 2; ks++) {
            uint32_t ah[2][4], al[2][4];
#pragma unroll
            for (int fm = 0; fm < 2; fm++) {
                uint32_t r = SW((uint32_t)((wm * 32 + fm * 16 + a_row) * ROWB + ks * 32 + a_kb));
                ldsm_x4(bb + OFF_AH + r, ah[fm]);
                ldsm_x4(bb + OFF_AL + r, al[fm]);
            }
#pragma unroll
            for (int h = 0; h < 2; h++) {
                uint32_t bhr[4][2], blr[4][2];
#pragma unroll
                for (int g = 0; g < 2; g++) {
                    uint32_t r = SW((uint32_t)((wn * 64 + h * 32 + g * 16 + b_row) * ROWB + ks * 32 + b_kb));
                    uint32_t t4[4];
                    ldsm_x4(bb + OFF_BH + r, t4);
                    bhr[g * 2][0] = t4[0]; bhr[g * 2][1] = t4[1];
                    bhr[g * 2 + 1][0] = t4[2]; bhr[g * 2 + 1][1] = t4[3];
                    ldsm_x4(bb + OFF_BL + r, t4);
                    blr[g * 2][0] = t4[0]; blr[g * 2][1] = t4[1];
                    blr[g * 2 + 1][0] = t4[2]; blr[g * 2 + 1][1] = t4[3];
                }
#pragma unroll
                for (int fm = 0; fm < 2; fm++)
#pragma unroll
                    for (int fl = 0; fl < 4; fl++)
                        mma_bf16(acc[fm][h * 4 + fl], ah[fm], bhr[fl]);
#pragma unroll
                for (int fm = 0; fm < 2; fm++)
#pragma unroll
                    for (int fl = 0; fl < 4; fl++)
                        mma_bf16(acc[fm][h * 4 + fl], ah[fm], blr[fl]);
#pragma unroll
                for (int fm = 0; fm < 2; fm++)
#pragma unroll
                    for (int fl = 0; fl < 4; fl++)
                        mma_bf16(acc[fm][h * 4 + fl], al[fm], bhr[fl]);
            }
        }
        if (++buf == NSTAGE) buf = 0;
    }

    const float scale = 0.04419417382415922f;      // 1/sqrt(512)
    if (FIRST) {
        float* S = g_S + (size_t)b * Ln;
        __nv_bfloat16* Ph = g_P_hi + (size_t)b * Ln * Ln;
        __nv_bfloat16* Pl = g_P_lo + (size_t)b * Ln * Ln;
#pragma unroll
        for (int fm = 0; fm < 2; fm++) {
            const int r0 = m0 + wm * 32 + fm * 16 + (lane >> 2);
            float rs0 = 0.0f, rs1 = 0.0f;
#pragma unroll
            for (int fn = 0; fn < 8; fn++) {
                int cl = wn * 64 + fn * 8 + (lane & 3) * 2;
                float me0 = lmp[cl], me1 = lmp[cl + 1];
                float v0 = expf(acc[fm][fn][0] * scale) * me0;
                float v1 = expf(acc[fm][fn][1] * scale) * me1;
                float v2 = expf(acc[fm][fn][2] * scale) * me0;
                float v3 = expf(acc[fm][fn][3] * scale) * me1;
                rs0 += v0 + v1;
                rs1 += v2 + v3;
                __nv_bfloat16 h0, l0, h1, l1, h2, l2, h3, l3;
                split_bf16(v0, h0, l0); split_bf16(v1, h1, l1);
                split_bf16(v2, h2, l2); split_bf16(v3, h3, l3);
                size_t o0 = (size_t)r0 * Ln + n0 + cl;
                size_t o1 = (size_t)(r0 + 8) * Ln + n0 + cl;
                *(__nv_bfloat162*)&Ph[o0] = __nv_bfloat162(h0, h1);
                *(__nv_bfloat162*)&Pl[o0] = __nv_bfloat162(l0, l1);
                *(__nv_bfloat162*)&Ph[o1] = __nv_bfloat162(h2, h3);
                *(__nv_bfloat162*)&Pl[o1] = __nv_bfloat162(l2, l3);
            }
            rs0 += __shfl_xor_sync(0xffffffffu, rs0, 1);
            rs0 += __shfl_xor_sync(0xffffffffu, rs0, 2);
            rs1 += __shfl_xor_sync(0xffffffffu, rs1, 1);
            rs1 += __shfl_xor_sync(0xffffffffu, rs1, 2);
            if ((lane & 3) == 0) {
                atomicAdd(&S[r0], rs0);
                atomicAdd(&S[r0 + 8], rs1);
            }
        }
    } else {
        float* D = Dout + (size_t)b * Cn * Ln;
#pragma unroll
        for (int fm = 0; fm < 2; fm++)
#pragma unroll
            for (int fn = 0; fn < 8; fn++) {
                int r0 = m0 + wm * 32 + fm * 16 + (lane >> 2);
                int cl = wn * 64 + fn * 8 + (lane & 3) * 2;
                float i0 = lmp[cl], i1 = lmp[cl + 1];
                *(float2*)&D[(size_t)r0 * Ln + n0 + cl] =
                    make_float2(acc[fm][fn][0] * i0, acc[fm][fn][1] * i1);
                *(float2*)&D[(size_t)(r0 + 8) * Ln + n0 + cl] =
                    make_float2(acc[fm][fn][2] * i0, acc[fm][fn][3] * i1);
            }
    }
}

// ---------------------------------------------------------------------------
// Zero the row-sum accumulators (graph-replay safe)
// ---------------------------------------------------------------------------
__global__ void zeroS_kernel()
{
    g_S[blockIdx.x * 256 + threadIdx.x] = 0.0f;
}

// ---------------------------------------------------------------------------
// Convert + transpose Q,K: [b][C][L] fp32 -> [b][L][C] bf16 hi/lo
// ---------------------------------------------------------------------------
template <bool ISQ>
__global__ void convT_kernel(const float* __restrict__ X)
{
    __shared__ float tile[32][33];
    const int b = blockIdx.z, l0 = blockIdx.x * 32, c0 = blockIdx.y * 32;
    const int tx = threadIdx.x, ty = threadIdx.y;
#pragma unroll
    for (int r = 0; r < 32; r += 8)
        tile[ty + r][tx] = X[((size_t)b * Cn + c0 + ty + r) * Ln + l0 + tx];
    __syncthreads();
    __nv_bfloat16* Hi = ISQ ? g_Qt_hi : g_Kt_hi;
    __nv_bfloat16* Lo = ISQ ? g_Qt_lo : g_Kt_lo;
#pragma unroll
    for (int r = 0; r < 32; r += 8) {
        float v = tile[tx][ty + r];
        __nv_bfloat16 h, l; split_bf16(v, h, l);
        size_t idx = ((size_t)b * Ln + l0 + ty + r) * Cn + c0 + tx;
        Hi[idx] = h; Lo[idx] = l;
    }
}

// Convert V: fp32 -> bf16 hi/lo of V*mask (mask folded in; [b][C][L] layout)
__global__ void convV_kernel(const float* __restrict__ V, const float* __restrict__ mask)
{
    size_t idx = ((size_t)blockIdx.x * 256 + threadIdx.x) * 2;
    const int b = (int)(idx / ((size_t)Cn * Ln));
    const int j = (int)(idx % Ln);
    float2 v = *(const float2*)(V + idx);
    float2 m = *(const float2*)(mask + (size_t)b * Ln + j);
    float a = v.x * m.x, c = v.y * m.y;
    __nv_bfloat16 h0, l0, h1, l1;
    split_bf16(a, h0, l0); split_bf16(c, h1, l1);
    *(__nv_bfloat162*)(g_V_hi + idx) = __nv_bfloat162(h0, h1);
    *(__nv_bfloat162*)(g_V_lo + idx) = __nv_bfloat162(l0, l1);
}

// ---------------------------------------------------------------------------
// attOut: attention output only.
//   attT[b][j][i] = (P_hi+P_lo)[i][j] * (1/S_i) * mask_j    (64x64 transpose)
// ---------------------------------------------------------------------------
__global__ __launch_bounds__(256) void attOut_kernel(float* __restrict__ AT,
                                                     const float* __restrict__ mask)
{
    __shared__ float tile[64][65];
    __shared__ float sinv[64], smask[64];
    const int b = blockIdx.z, j0 = blockIdx.x * 64, i0 = blockIdx.y * 64;
    const int t = threadIdx.x;
    const int r = t >> 2;            // 0..63 (row i0+r)
    const int seg = t & 3;           // 16 contiguous j's each

    if (t < 64)       sinv[t] = 1.0f / g_S[(size_t)b * Ln + i0 + t];
    else if (t < 128) smask[t - 64] = mask[(size_t)b * Ln + j0 + (t - 64)];
    __syncthreads();

    {
        size_t src = ((size_t)b * Ln + i0 + r) * Ln + j0 + seg * 16;
        uint4 h0 = *(const uint4*)&g_P_hi[src];
        uint4 h1 = *(const uint4*)&g_P_hi[src + 8];
        uint4 l0 = *(const uint4*)&g_P_lo[src];
        uint4 l1 = *(const uint4*)&g_P_lo[src + 8];
        const uint32_t* hw  = (const uint32_t*)&h0;
        const uint32_t* hw1 = (const uint32_t*)&h1;
        const uint32_t* lw  = (const uint32_t*)&l0;
        const uint32_t* lw1 = (const uint32_t*)&l1;
        const float inv = sinv[r];
#pragma unroll
        for (int k = 0; k < 4; k++) {
            __nv_bfloat162 hp = *(__nv_bfloat162*)&hw[k];
            __nv_bfloat162 lp = *(__nv_bfloat162*)&lw[k];
            tile[r][seg * 16 + 2 * k]     = (__bfloat162float(hp.x) + __bfloat162float(lp.x)) * inv * smask[seg * 16 + 2 * k];
            tile[r][seg * 16 + 2 * k + 1] = (__bfloat162float(hp.y) + __bfloat162float(lp.y)) * inv * smask[seg * 16 + 2 * k + 1];
        }
#pragma unroll
        for (int k = 0; k < 4; k++) {
            __nv_bfloat162 hp = *(__nv_bfloat162*)&hw1[k];
            __nv_bfloat162 lp = *(__nv_bfloat162*)&lw1[k];
            tile[r][seg * 16 + 8 + 2 * k]     = (__bfloat162float(hp.x) + __bfloat162float(lp.x)) * inv * smask[seg * 16 + 8 + 2 * k];
            tile[r][seg * 16 + 8 + 2 * k + 1] = (__bfloat162float(hp.y) + __bfloat162float(lp.y)) * inv * smask[seg * 16 + 8 + 2 * k + 1];
        }
    }
    __syncthreads();

    float o[16];
#pragma unroll
    for (int k = 0; k < 16; k++)
        o[k] = tile[seg * 16 + k][r];
    float* dst = AT + ((size_t)b * Ln + j0 + r) * Ln + i0 + seg * 16;
#pragma unroll
    for (int q = 0; q < 4; q++)
        *(float4*)&dst[q * 4] = *(float4*)&o[q * 4];
}

// ---------------------------------------------------------------------------
extern "C" void kernel_launch(void* const* d_in, const int* in_sizes, int n_in,
                              void* d_out, int out_size)
{
    const float* Q    = (const float*)d_in[0];
    const float* Kt   = (const float*)d_in[1];
    const float* V    = (const float*)d_in[2];
    const float* mask = (const float*)d_in[3];

    float* out  = (float*)d_out;                   // (B, C, L)
    float* attT = out + (size_t)Bn * Cn * Ln;      // (B, L, L)

    cudaFuncSetAttribute(mma_gemm_kernel<true>,
                         cudaFuncAttributeMaxDynamicSharedMemorySize, SMEM_BYTES);
    cudaFuncSetAttribute(mma_gemm_kernel<false>,
                         cudaFuncAttributeMaxDynamicSharedMemorySize, SMEM_BYTES);

    zeroS_kernel<<<(Bn * Ln) / 256, 256>>>();
    convT_kernel<true><<<dim3(Ln / 32, Cn / 32, Bn), dim3(32, 8)>>>(Q);
    convT_kernel<false><<<dim3(Ln / 32, Cn / 32, Bn), dim3(32, 8)>>>(Kt);
    convV_kernel<<<(int)(((size_t)Bn * Cn * Ln) / 512), 256>>>(V, mask);

    mma_gemm_kernel<true><<<dim3(Ln / 128, Ln / 128, Bn), 256, SMEM_BYTES>>>(nullptr, mask);
    mma_gemm_kernel<false><<<dim3(Cn / 128, Ln / 128, Bn), 256, SMEM_BYTES>>>(out, nullptr);
    attOut_kernel<<<dim3(Ln / 64, Ln / 64, Bn), 256>>>(attT, mask);
}

// round 10
// speedup vs baseline: 1.3710x; 1.1600x over previous
#include <cuda_runtime.h>
#include <cuda_bf16.h>
#include <cuda_fp16.h>
#include <math.h>
#include <stdint.h>

#define Bn 4
#define Cn 512
#define Ln 4096

// ---------------------------------------------------------------------------
// Scratch (static device globals; no allocation allowed)
// ---------------------------------------------------------------------------
__device__ float g_S[(size_t)Bn * Ln];                         // row sums of exp_un
__device__ __nv_bfloat16 g_Qt_hi[(size_t)Bn * Ln * Cn];        // Q^T  [b][i][c]
__device__ __nv_bfloat16 g_Qt_lo[(size_t)Bn * Ln * Cn];
__device__ __nv_bfloat16 g_Kt_hi[(size_t)Bn * Ln * Cn];        // K^T  [b][j][c]
__device__ __nv_bfloat16 g_Kt_lo[(size_t)Bn * Ln * Cn];
__device__ __half g_V[(size_t)Bn * Cn * Ln];                   // fp16(V*mask) [b][c][j]
__device__ __half g_P_hi[(size_t)Bn * Ln * Ln];                // exp_un hi [b][i][j]
__device__ __half g_P_lo[(size_t)Bn * Ln * Ln];                // exp_un lo

// ---------------------------------------------------------------------------
// Base-ISA helpers (compute_103-safe: ldmatrix / mma.sync / cp.async)
// ---------------------------------------------------------------------------
__device__ __forceinline__ uint32_t smem_u32(const void* p) {
    uint32_t a;
    asm("{ .reg .u64 t; cvta.to.shared.u64 t, %1; cvt.u32.u64 %0, t; }" : "=r"(a) : "l"(p));
    return a;
}
__device__ __forceinline__ void ldsm_x4(uint32_t addr, uint32_t r[4]) {
    asm volatile("ldmatrix.sync.aligned.m8n8.x4.shared.b16 {%0,%1,%2,%3}, [%4];"
                 : "=r"(r[0]), "=r"(r[1]), "=r"(r[2]), "=r"(r[3]) : "r"(addr));
}
__device__ __forceinline__ void mma_bf16(float d[4], const uint32_t a[4], const uint32_t b[2]) {
    asm volatile("mma.sync.aligned.m16n8k16.row.col.f32.bf16.bf16.f32 "
                 "{%0,%1,%2,%3}, {%4,%5,%6,%7}, {%8,%9}, {%0,%1,%2,%3};"
                 : "+f"(d[0]), "+f"(d[1]), "+f"(d[2]), "+f"(d[3])
                 : "r"(a[0]), "r"(a[1]), "r"(a[2]), "r"(a[3]), "r"(b[0]), "r"(b[1]));
}
__device__ __forceinline__ void mma_f16(float d[4], const uint32_t a[4], const uint32_t b[2]) {
    asm volatile("mma.sync.aligned.m16n8k16.row.col.f32.f16.f16.f32 "
                 "{%0,%1,%2,%3}, {%4,%5,%6,%7}, {%8,%9}, {%0,%1,%2,%3};"
                 : "+f"(d[0]), "+f"(d[1]), "+f"(d[2]), "+f"(d[3])
                 : "r"(a[0]), "r"(a[1]), "r"(a[2]), "r"(a[3]), "r"(b[0]), "r"(b[1]));
}
#define CP16(d, s) asm volatile("cp.async.cg.shared.global [%0], [%1], 16;" :: "r"(d), "l"(s))
#define CP_COMMIT() asm volatile("cp.async.commit_group;" ::: "memory")
#define CP_WAIT1()  asm volatile("cp.async.wait_group 1;" ::: "memory")
#define CP_WAIT0()  asm volatile("cp.async.wait_group 0;" ::: "memory")

__device__ __forceinline__ void split_bf16(float x, __nv_bfloat16& h, __nv_bfloat16& l) {
    h = __float2bfloat16(x);
    l = __float2bfloat16(x - __bfloat162float(h));
}
__device__ __forceinline__ void split_f16(float x, __half& h, __half& l) {
    h = __float2half(x);
    l = __float2half(x - __half2float(h));
}

// ---------------------------------------------------------------------------
// smem geometry: tiles of 128 rows x 32 elems (2B) = 64 B rows, XOR-swizzled.
// GEMM1: 4 tiles (QtHi,QtLo,KtHi,KtLo). GEMM2: 3 tiles (V, Phi, Plo).
// Triple buffered; regs capped at 128 -> 2 CTAs/SM.
// ---------------------------------------------------------------------------
#define SW(o) ((o) ^ (((o) >> 3) & 0x30))
#define ROWB 64
#define TILE_B (128 * ROWB)        // 8192
#define NSTAGE 3

// ---------------------------------------------------------------------------
// tensor-core GEMM, 128x128 tile, BK=32, 256 threads, 3-stage pipeline.
// FIRST (bf16 x3): P_un[i][j] = exp(QtK*scale)*(mask+1e-6) fp16 hi/lo; sums->g_S
// !FIRST (fp16 x2): out[c][i] = (Σ_j V'[c][j]·P_un[i][j]) / S_i
// ---------------------------------------------------------------------------
template <bool FIRST>
__global__ __launch_bounds__(256, 2) void mma_gemm_kernel(float* __restrict__ Dout,
                                                          const float* __restrict__ mask)
{
    constexpr int KTOT = FIRST ? Cn : Ln;
    constexpr int LD   = FIRST ? Cn : Ln;
    constexpr int NIT  = KTOT / 32;
    constexpr int NTILE = FIRST ? 4 : 3;
    constexpr int BUFB = NTILE * TILE_B;
    constexpr int LMOFF = NSTAGE * BUFB;

    extern __shared__ char smem[];
    const uint32_t sbase = smem_u32(smem);
    const int tid = threadIdx.x;
    const int b = blockIdx.z;
    const int n0 = (FIRST ? blockIdx.x : blockIdx.y) * 128;
    const int m0 = (FIRST ? blockIdx.y : blockIdx.x) * 128;

    // operand base pointers
    const __nv_bfloat16* Ah = g_Qt_hi + ((size_t)b * Ln + m0) * Cn;
    const __nv_bfloat16* Al = g_Qt_lo + ((size_t)b * Ln + m0) * Cn;
    const __nv_bfloat16* Bh = g_Kt_hi + ((size_t)b * Ln + n0) * Cn;
    const __nv_bfloat16* Bl = g_Kt_lo + ((size_t)b * Ln + n0) * Cn;
    const __half* Av  = g_V    + ((size_t)b * Cn + m0) * Ln;
    const __half* Bph = g_P_hi + ((size_t)b * Ln + n0) * Ln;
    const __half* Bpl = g_P_lo + ((size_t)b * Ln + n0) * Ln;

    float* lmp = (float*)(smem + LMOFF);
    if (FIRST) {
        if (tid < 128) lmp[tid] = mask[(size_t)b * Ln + n0 + tid] + 1e-6f;
    } else {
        if (tid < 128) lmp[tid] = 1.0f / g_S[(size_t)b * Ln + n0 + tid];
    }

    const int lane = tid & 31, wid = tid >> 5;
    const int wm = wid & 3, wn = wid >> 2;
    const int quad = lane >> 3, qj = lane & 7;
    const int a_row = (quad & 1) * 8 + qj;
    const int a_kb  = (quad >> 1) * 16;
    const int b_row = (quad >> 1) * 8 + qj;
    const int b_kb  = (quad & 1) * 16;

    float acc[2][8][4];
#pragma unroll
    for (int fm = 0; fm < 2; fm++)
#pragma unroll
        for (int fn = 0; fn < 8; fn++)
#pragma unroll
            for (int e = 0; e < 4; e++) acc[fm][fn][e] = 0.0f;

    auto load_slab = [&](int buf, int it) {
        const uint32_t bb = sbase + buf * BUFB;
        const int k0 = it * 32;
#pragma unroll
        for (int t = 0; t < 2; t++) {
            int f = t * 256 + tid;
            int row = f >> 2, ch = f & 3;
            uint32_t doff = SW((uint32_t)(row * ROWB + ch * 16));
            size_t soff = (size_t)row * LD + k0 + ch * 8;
            if (FIRST) {
                CP16(bb + 0 * TILE_B + doff, Ah + soff);
                CP16(bb + 1 * TILE_B + doff, Al + soff);
                CP16(bb + 2 * TILE_B + doff, Bh + soff);
                CP16(bb + 3 * TILE_B + doff, Bl + soff);
            } else {
                CP16(bb + 0 * TILE_B + doff, Av + soff);
                CP16(bb + 1 * TILE_B + doff, Bph + soff);
                CP16(bb + 2 * TILE_B + doff, Bpl + soff);
            }
        }
        CP_COMMIT();
    };

    load_slab(0, 0);
    load_slab(1, 1);

    int buf = 0;
    for (int it = 0; it < NIT; it++) {
        if (it + 1 < NIT) { CP_WAIT1(); } else { CP_WAIT0(); }
        __syncthreads();
        if (it + 2 < NIT) {
            int nb = buf + 2; if (nb >= NSTAGE) nb -= NSTAGE;
            load_slab(nb, it + 2);
        }

        const uint32_t bb = sbase + buf * BUFB;
#pragma unroll
        for (int ks = 0; ks < 2; ks++) {
            if (FIRST) {
                uint32_t ah[2][4], al[2][4];
#pragma unroll
                for (int fm = 0; fm < 2; fm++) {
                    uint32_t r = SW((uint32_t)((wm * 32 + fm * 16 + a_row) * ROWB + ks * 32 + a_kb));
                    ldsm_x4(bb + 0 * TILE_B + r, ah[fm]);
                    ldsm_x4(bb + 1 * TILE_B + r, al[fm]);
                }
#pragma unroll
                for (int h = 0; h < 2; h++) {
                    uint32_t bhr[4][2], blr[4][2];
#pragma unroll
                    for (int g = 0; g < 2; g++) {
                        uint32_t r = SW((uint32_t)((wn * 64 + h * 32 + g * 16 + b_row) * ROWB + ks * 32 + b_kb));
                        uint32_t t4[4];
                        ldsm_x4(bb + 2 * TILE_B + r, t4);
                        bhr[g * 2][0] = t4[0]; bhr[g * 2][1] = t4[1];
                        bhr[g * 2 + 1][0] = t4[2]; bhr[g * 2 + 1][1] = t4[3];
                        ldsm_x4(bb + 3 * TILE_B + r, t4);
                        blr[g * 2][0] = t4[0]; blr[g * 2][1] = t4[1];
                        blr[g * 2 + 1][0] = t4[2]; blr[g * 2 + 1][1] = t4[3];
                    }
#pragma unroll
                    for (int fm = 0; fm < 2; fm++)
#pragma unroll
                        for (int fl = 0; fl < 4; fl++)
                            mma_bf16(acc[fm][h * 4 + fl], ah[fm], bhr[fl]);
#pragma unroll
                    for (int fm = 0; fm < 2; fm++)
#pragma unroll
                        for (int fl = 0; fl < 4; fl++)
                            mma_bf16(acc[fm][h * 4 + fl], ah[fm], blr[fl]);
#pragma unroll
                    for (int fm = 0; fm < 2; fm++)
#pragma unroll
                        for (int fl = 0; fl < 4; fl++)
                            mma_bf16(acc[fm][h * 4 + fl], al[fm], bhr[fl]);
                }
            } else {
                uint32_t ah[2][4];
#pragma unroll
                for (int fm = 0; fm < 2; fm++) {
                    uint32_t r = SW((uint32_t)((wm * 32 + fm * 16 + a_row) * ROWB + ks * 32 + a_kb));
                    ldsm_x4(bb + 0 * TILE_B + r, ah[fm]);
                }
#pragma unroll
                for (int h = 0; h < 2; h++) {
                    uint32_t bhr[4][2], blr[4][2];
#pragma unroll
                    for (int g = 0; g < 2; g++) {
                        uint32_t r = SW((uint32_t)((wn * 64 + h * 32 + g * 16 + b_row) * ROWB + ks * 32 + b_kb));
                        uint32_t t4[4];
                        ldsm_x4(bb + 1 * TILE_B + r, t4);
                        bhr[g * 2][0] = t4[0]; bhr[g * 2][1] = t4[1];
                        bhr[g * 2 + 1][0] = t4[2]; bhr[g * 2 + 1][1] = t4[3];
                        ldsm_x4(bb + 2 * TILE_B + r, t4);
                        blr[g * 2][0] = t4[0]; blr[g * 2][1] = t4[1];
                        blr[g * 2 + 1][0] = t4[2]; blr[g * 2 + 1][1] = t4[3];
                    }
#pragma unroll
                    for (int fm = 0; fm < 2; fm++)
#pragma unroll
                        for (int fl = 0; fl < 4; fl++)
                            mma_f16(acc[fm][h * 4 + fl], ah[fm], bhr[fl]);
#pragma unroll
                    for (int fm = 0; fm < 2; fm++)
#pragma unroll
                        for (int fl = 0; fl < 4; fl++)
                            mma_f16(acc[fm][h * 4 + fl], ah[fm], blr[fl]);
                }
            }
        }
        if (++buf == NSTAGE) buf = 0;
    }

    const float scale = 0.04419417382415922f;      // 1/sqrt(512)
    if (FIRST) {
        float* S = g_S + (size_t)b * Ln;
        __half* Ph = g_P_hi + (size_t)b * Ln * Ln;
        __half* Pl = g_P_lo + (size_t)b * Ln * Ln;
#pragma unroll
        for (int fm = 0; fm < 2; fm++) {
            const int r0 = m0 + wm * 32 + fm * 16 + (lane >> 2);
            float rs0 = 0.0f, rs1 = 0.0f;
#pragma unroll
            for (int fn = 0; fn < 8; fn++) {
                int cl = wn * 64 + fn * 8 + (lane & 3) * 2;
                float me0 = lmp[cl], me1 = lmp[cl + 1];
                float v0 = expf(acc[fm][fn][0] * scale) * me0;
                float v1 = expf(acc[fm][fn][1] * scale) * me1;
                float v2 = expf(acc[fm][fn][2] * scale) * me0;
                float v3 = expf(acc[fm][fn][3] * scale) * me1;
                rs0 += v0 + v1;
                rs1 += v2 + v3;
                __half h0, l0, h1, l1, h2, l2, h3, l3;
                split_f16(v0, h0, l0); split_f16(v1, h1, l1);
                split_f16(v2, h2, l2); split_f16(v3, h3, l3);
                size_t o0 = (size_t)r0 * Ln + n0 + cl;
                size_t o1 = (size_t)(r0 + 8) * Ln + n0 + cl;
                *(__half2*)&Ph[o0] = __halves2half2(h0, h1);
                *(__half2*)&Pl[o0] = __halves2half2(l0, l1);
                *(__half2*)&Ph[o1] = __halves2half2(h2, h3);
                *(__half2*)&Pl[o1] = __halves2half2(l2, l3);
            }
            rs0 += __shfl_xor_sync(0xffffffffu, rs0, 1);
            rs0 += __shfl_xor_sync(0xffffffffu, rs0, 2);
            rs1 += __shfl_xor_sync(0xffffffffu, rs1, 1);
            rs1 += __shfl_xor_sync(0xffffffffu, rs1, 2);
            if ((lane & 3) == 0) {
                atomicAdd(&S[r0], rs0);
                atomicAdd(&S[r0 + 8], rs1);
            }
        }
    } else {
        float* D = Dout + (size_t)b * Cn * Ln;
#pragma unroll
        for (int fm = 0; fm < 2; fm++)
#pragma unroll
            for (int fn = 0; fn < 8; fn++) {
                int r0 = m0 + wm * 32 + fm * 16 + (lane >> 2);
                int cl = wn * 64 + fn * 8 + (lane & 3) * 2;
                float i0 = lmp[cl], i1 = lmp[cl + 1];
                *(float2*)&D[(size_t)r0 * Ln + n0 + cl] =
                    make_float2(acc[fm][fn][0] * i0, acc[fm][fn][1] * i1);
                *(float2*)&D[(size_t)(r0 + 8) * Ln + n0 + cl] =
                    make_float2(acc[fm][fn][2] * i0, acc[fm][fn][3] * i1);
            }
    }
}

#define SMEM1_BYTES (NSTAGE * 4 * TILE_B + 512)
#define SMEM2_BYTES (NSTAGE * 3 * TILE_B + 512)

// ---------------------------------------------------------------------------
// Convert + transpose Q,K: [b][C][L] fp32 -> [b][L][C] bf16 hi/lo
// ---------------------------------------------------------------------------
template <bool ISQ>
__global__ void convT_kernel(const float* __restrict__ X)
{
    __shared__ float tile[32][33];
    const int b = blockIdx.z, l0 = blockIdx.x * 32, c0 = blockIdx.y * 32;
    const int tx = threadIdx.x, ty = threadIdx.y;
#pragma unroll
    for (int r = 0; r < 32; r += 8)
        tile[ty + r][tx] = X[((size_t)b * Cn + c0 + ty + r) * Ln + l0 + tx];
    __syncthreads();
    __nv_bfloat16* Hi = ISQ ? g_Qt_hi : g_Kt_hi;
    __nv_bfloat16* Lo = ISQ ? g_Qt_lo : g_Kt_lo;
#pragma unroll
    for (int r = 0; r < 32; r += 8) {
        float v = tile[tx][ty + r];
        __nv_bfloat16 h, l; split_bf16(v, h, l);
        size_t idx = ((size_t)b * Ln + l0 + ty + r) * Cn + c0 + tx;
        Hi[idx] = h; Lo[idx] = l;
    }
}

// Convert V: fp32 -> fp16 of V*mask (mask folded in). Also zeroes g_S.
__global__ void convV_kernel(const float* __restrict__ V, const float* __restrict__ mask)
{
    if (blockIdx.x < (Bn * Ln) / 256)
        g_S[(size_t)blockIdx.x * 256 + threadIdx.x] = 0.0f;
    size_t idx = ((size_t)blockIdx.x * 256 + threadIdx.x) * 2;
    const int b = (int)(idx / ((size_t)Cn * Ln));
    const int j = (int)(idx % Ln);
    float2 v = *(const float2*)(V + idx);
    float2 m = *(const float2*)(mask + (size_t)b * Ln + j);
    *(__half2*)(g_V + idx) = __floats2half2_rn(v.x * m.x, v.y * m.y);
}

// ---------------------------------------------------------------------------
// attOut: attention output only.
//   attT[b][j][i] = (P_hi+P_lo)[i][j] * (1/S_i) * mask_j    (64x64 transpose)
// ---------------------------------------------------------------------------
__global__ __launch_bounds__(256) void attOut_kernel(float* __restrict__ AT,
                                                     const float* __restrict__ mask)
{
    __shared__ float tile[64][65];
    __shared__ float sinv[64], smask[64];
    const int b = blockIdx.z, j0 = blockIdx.x * 64, i0 = blockIdx.y * 64;
    const int t = threadIdx.x;
    const int r = t >> 2;            // 0..63 (row i0+r)
    const int seg = t & 3;           // 16 contiguous j's each

    if (t < 64)       sinv[t] = 1.0f / g_S[(size_t)b * Ln + i0 + t];
    else if (t < 128) smask[t - 64] = mask[(size_t)b * Ln + j0 + (t - 64)];
    __syncthreads();

    {
        size_t src = ((size_t)b * Ln + i0 + r) * Ln + j0 + seg * 16;
        uint4 h0 = *(const uint4*)&g_P_hi[src];
        uint4 h1 = *(const uint4*)&g_P_hi[src + 8];
        uint4 l0 = *(const uint4*)&g_P_lo[src];
        uint4 l1 = *(const uint4*)&g_P_lo[src + 8];
        const uint32_t* hw  = (const uint32_t*)&h0;
        const uint32_t* hw1 = (const uint32_t*)&h1;
        const uint32_t* lw  = (const uint32_t*)&l0;
        const uint32_t* lw1 = (const uint32_t*)&l1;
        const float inv = sinv[r];
#pragma unroll
        for (int k = 0; k < 4; k++) {
            float2 hp = __half22float2(*(__half2*)&hw[k]);
            float2 lp = __half22float2(*(__half2*)&lw[k]);
            tile[r][seg * 16 + 2 * k]     = (hp.x + lp.x) * inv * smask[seg * 16 + 2 * k];
            tile[r][seg * 16 + 2 * k + 1] = (hp.y + lp.y) * inv * smask[seg * 16 + 2 * k + 1];
        }
#pragma unroll
        for (int k = 0; k < 4; k++) {
            float2 hp = __half22float2(*(__half2*)&hw1[k]);
            float2 lp = __half22float2(*(__half2*)&lw1[k]);
            tile[r][seg * 16 + 8 + 2 * k]     = (hp.x + lp.x) * inv * smask[seg * 16 + 8 + 2 * k];
            tile[r][seg * 16 + 8 + 2 * k + 1] = (hp.y + lp.y) * inv * smask[seg * 16 + 8 + 2 * k + 1];
        }
    }
    __syncthreads();

    float o[16];
#pragma unroll
    for (int k = 0; k < 16; k++)
        o[k] = tile[seg * 16 + k][r];
    float* dst = AT + ((size_t)b * Ln + j0 + r) * Ln + i0 + seg * 16;
#pragma unroll
    for (int q = 0; q < 4; q++)
        *(float4*)&dst[q * 4] = *(float4*)&o[q * 4];
}

// ---------------------------------------------------------------------------
extern "C" void kernel_launch(void* const* d_in, const int* in_sizes, int n_in,
                              void* d_out, int out_size)
{
    const float* Q    = (const float*)d_in[0];
    const float* Kt   = (const float*)d_in[1];
    const float* V    = (const float*)d_in[2];
    const float* mask = (const float*)d_in[3];

    float* out  = (float*)d_out;                   // (B, C, L)
    float* attT = out + (size_t)Bn * Cn * Ln;      // (B, L, L)

    cudaFuncSetAttribute(mma_gemm_kernel<true>,
                         cudaFuncAttributeMaxDynamicSharedMemorySize, SMEM1_BYTES);
    cudaFuncSetAttribute(mma_gemm_kernel<false>,
                         cudaFuncAttributeMaxDynamicSharedMemorySize, SMEM2_BYTES);

    convT_kernel<true><<<dim3(Ln / 32, Cn / 32, Bn), dim3(32, 8)>>>(Q);
    convT_kernel<false><<<dim3(Ln / 32, Cn / 32, Bn), dim3(32, 8)>>>(Kt);
    convV_kernel<<<(int)(((size_t)Bn * Cn * Ln) / 512), 256>>>(V, mask);

    mma_gemm_kernel<true><<<dim3(Ln / 128, Ln / 128, Bn), 256, SMEM1_BYTES>>>(nullptr, mask);
    mma_gemm_kernel<false><<<dim3(Cn / 128, Ln / 128, Bn), 256, SMEM2_BYTES>>>(out, nullptr);
    attOut_kernel<<<dim3(Ln / 64, Ln / 64, Bn), 256>>>(attT, mask);
}

// round 11
// speedup vs baseline: 1.5892x; 1.1592x over previous
#include <cuda_runtime.h>
#include <cuda_bf16.h>
#include <cuda_fp16.h>
#include <math.h>
#include <stdint.h>

#define Bn 4
#define Cn 512
#define Ln 4096

// ---------------------------------------------------------------------------
// Scratch (static device globals; no allocation allowed)
// ---------------------------------------------------------------------------
__device__ float g_S[(size_t)Bn * Ln];                         // row sums of exp_un
__device__ __half g_Qt[(size_t)Bn * Ln * Cn];                  // fp16(Q^T) [b][i][c]
__device__ __half g_Kt_hi[(size_t)Bn * Ln * Cn];               // K^T hi [b][j][c]
__device__ __half g_Kt_lo[(size_t)Bn * Ln * Cn];               // K^T lo
__device__ __half g_V[(size_t)Bn * Cn * Ln];                   // fp16(V*mask) [b][c][j]
__device__ __half g_P_hi[(size_t)Bn * Ln * Ln];                // exp_un hi [b][i][j]
__device__ __half g_P_lo[(size_t)Bn * Ln * Ln];                // exp_un lo

// ---------------------------------------------------------------------------
// Base-ISA helpers (compute_103-safe: ldmatrix / mma.sync / cp.async)
// ---------------------------------------------------------------------------
__device__ __forceinline__ uint32_t smem_u32(const void* p) {
    uint32_t a;
    asm("{ .reg .u64 t; cvta.to.shared.u64 t, %1; cvt.u32.u64 %0, t; }" : "=r"(a) : "l"(p));
    return a;
}
__device__ __forceinline__ void ldsm_x4(uint32_t addr, uint32_t r[4]) {
    asm volatile("ldmatrix.sync.aligned.m8n8.x4.shared.b16 {%0,%1,%2,%3}, [%4];"
                 : "=r"(r[0]), "=r"(r[1]), "=r"(r[2]), "=r"(r[3]) : "r"(addr));
}
__device__ __forceinline__ void mma_f16(float d[4], const uint32_t a[4], const uint32_t b[2]) {
    asm volatile("mma.sync.aligned.m16n8k16.row.col.f32.f16.f16.f32 "
                 "{%0,%1,%2,%3}, {%4,%5,%6,%7}, {%8,%9}, {%0,%1,%2,%3};"
                 : "+f"(d[0]), "+f"(d[1]), "+f"(d[2]), "+f"(d[3])
                 : "r"(a[0]), "r"(a[1]), "r"(a[2]), "r"(a[3]), "r"(b[0]), "r"(b[1]));
}
#define CP16(d, s) asm volatile("cp.async.cg.shared.global [%0], [%1], 16;" :: "r"(d), "l"(s))
#define CP_COMMIT() asm volatile("cp.async.commit_group;" ::: "memory")
#define CP_WAIT1()  asm volatile("cp.async.wait_group 1;" ::: "memory")
#define CP_WAIT0()  asm volatile("cp.async.wait_group 0;" ::: "memory")

__device__ __forceinline__ void split_f16(float x, __half& h, __half& l) {
    h = __float2half(x);
    l = __float2half(x - __half2float(h));
}

// ---------------------------------------------------------------------------
// smem geometry: 3 tiles (A, Bhi, Blo), 128 rows x 32 fp16 = 64 B rows,
// XOR-swizzled. Triple buffered: 3 x 24 KB = 72 KB; 2 CTAs/SM.
// ---------------------------------------------------------------------------
#define SW(o) ((o) ^ (((o) >> 3) & 0x30))
#define ROWB 64
#define TILE_B (128 * ROWB)        // 8192
#define NSTAGE 3
#define BUFB (3 * TILE_B)          // 24576
#define LMOFF (NSTAGE * BUFB)      // 73728
#define SMEM_BYTES (LMOFF + 512)

// ---------------------------------------------------------------------------
// fp16 x2 tensor-core GEMM: acc = A·(Bhi + Blo). 128x128 tile, BK=32,
// 256 threads, 3-stage cp.async pipeline.
// FIRST: P_un[i][j] = exp((Qt·Kt)*scale)*(mask+1e-6) as fp16 hi/lo; sums->g_S
// !FIRST: out[c][i] = (Σ_j V'[c][j]·P_un[i][j]) / S_i
// ---------------------------------------------------------------------------
template <bool FIRST>
__global__ __launch_bounds__(256, 2) void mma_gemm_kernel(float* __restrict__ Dout,
                                                          const float* __restrict__ mask)
{
    constexpr int KTOT = FIRST ? Cn : Ln;
    constexpr int LD   = FIRST ? Cn : Ln;
    constexpr int NIT  = KTOT / 32;

    extern __shared__ char smem[];
    const uint32_t sbase = smem_u32(smem);
    const int tid = threadIdx.x;
    const int b = blockIdx.z;
    const int n0 = (FIRST ? blockIdx.x : blockIdx.y) * 128;
    const int m0 = (FIRST ? blockIdx.y : blockIdx.x) * 128;

    const __half* A  = (FIRST ? g_Qt   : g_V)    + ((size_t)b * (FIRST ? Ln : Cn) + m0) * LD;
    const __half* Bh = (FIRST ? g_Kt_hi : g_P_hi) + ((size_t)b * Ln + n0) * LD;
    const __half* Bl = (FIRST ? g_Kt_lo : g_P_lo) + ((size_t)b * Ln + n0) * LD;

    float* lmp = (float*)(smem + LMOFF);
    if (FIRST) {
        if (tid < 128) lmp[tid] = mask[(size_t)b * Ln + n0 + tid] + 1e-6f;
    } else {
        if (tid < 128) lmp[tid] = 1.0f / g_S[(size_t)b * Ln + n0 + tid];
    }

    const int lane = tid & 31, wid = tid >> 5;
    const int wm = wid & 3, wn = wid >> 2;
    const int quad = lane >> 3, qj = lane & 7;
    const int a_row = (quad & 1) * 8 + qj;
    const int a_kb  = (quad >> 1) * 16;
    const int b_row = (quad >> 1) * 8 + qj;
    const int b_kb  = (quad & 1) * 16;

    float acc[2][8][4];
#pragma unroll
    for (int fm = 0; fm < 2; fm++)
#pragma unroll
        for (int fn = 0; fn < 8; fn++)
#pragma unroll
            for (int e = 0; e < 4; e++) acc[fm][fn][e] = 0.0f;

    auto load_slab = [&](int buf, int it) {
        const uint32_t bb = sbase + buf * BUFB;
        const int k0 = it * 32;
#pragma unroll
        for (int t = 0; t < 2; t++) {
            int f = t * 256 + tid;
            int row = f >> 2, ch = f & 3;
            uint32_t doff = SW((uint32_t)(row * ROWB + ch * 16));
            size_t soff = (size_t)row * LD + k0 + ch * 8;
            CP16(bb + 0 * TILE_B + doff, A + soff);
            CP16(bb + 1 * TILE_B + doff, Bh + soff);
            CP16(bb + 2 * TILE_B + doff, Bl + soff);
        }
        CP_COMMIT();
    };

    load_slab(0, 0);
    load_slab(1, 1);

    int buf = 0;
    for (int it = 0; it < NIT; it++) {
        if (it + 1 < NIT) { CP_WAIT1(); } else { CP_WAIT0(); }
        __syncthreads();
        if (it + 2 < NIT) {
            int nb = buf + 2; if (nb >= NSTAGE) nb -= NSTAGE;
            load_slab(nb, it + 2);
        }

        const uint32_t bb = sbase + buf * BUFB;
#pragma unroll
        for (int ks = 0; ks < 2; ks++) {
            uint32_t ar[2][4];
#pragma unroll
            for (int fm = 0; fm < 2; fm++) {
                uint32_t r = SW((uint32_t)((wm * 32 + fm * 16 + a_row) * ROWB + ks * 32 + a_kb));
                ldsm_x4(bb + 0 * TILE_B + r, ar[fm]);
            }
#pragma unroll
            for (int h = 0; h < 2; h++) {
                uint32_t bhr[4][2], blr[4][2];
#pragma unroll
                for (int g = 0; g < 2; g++) {
                    uint32_t r = SW((uint32_t)((wn * 64 + h * 32 + g * 16 + b_row) * ROWB + ks * 32 + b_kb));
                    uint32_t t4[4];
                    ldsm_x4(bb + 1 * TILE_B + r, t4);
                    bhr[g * 2][0] = t4[0]; bhr[g * 2][1] = t4[1];
                    bhr[g * 2 + 1][0] = t4[2]; bhr[g * 2 + 1][1] = t4[3];
                    ldsm_x4(bb + 2 * TILE_B + r, t4);
                    blr[g * 2][0] = t4[0]; blr[g * 2][1] = t4[1];
                    blr[g * 2 + 1][0] = t4[2]; blr[g * 2 + 1][1] = t4[3];
                }
#pragma unroll
                for (int fm = 0; fm < 2; fm++)
#pragma unroll
                    for (int fl = 0; fl < 4; fl++)
                        mma_f16(acc[fm][h * 4 + fl], ar[fm], bhr[fl]);
#pragma unroll
                for (int fm = 0; fm < 2; fm++)
#pragma unroll
                    for (int fl = 0; fl < 4; fl++)
                        mma_f16(acc[fm][h * 4 + fl], ar[fm], blr[fl]);
            }
        }
        if (++buf == NSTAGE) buf = 0;
    }

    const float scale = 0.04419417382415922f;      // 1/sqrt(512)
    if (FIRST) {
        float* S = g_S + (size_t)b * Ln;
        __half* Ph = g_P_hi + (size_t)b * Ln * Ln;
        __half* Pl = g_P_lo + (size_t)b * Ln * Ln;
#pragma unroll
        for (int fm = 0; fm < 2; fm++) {
            const int r0 = m0 + wm * 32 + fm * 16 + (lane >> 2);
            float rs0 = 0.0f, rs1 = 0.0f;
#pragma unroll
            for (int fn = 0; fn < 8; fn++) {
                int cl = wn * 64 + fn * 8 + (lane & 3) * 2;
                float me0 = lmp[cl], me1 = lmp[cl + 1];
                float v0 = expf(acc[fm][fn][0] * scale) * me0;
                float v1 = expf(acc[fm][fn][1] * scale) * me1;
                float v2 = expf(acc[fm][fn][2] * scale) * me0;
                float v3 = expf(acc[fm][fn][3] * scale) * me1;
                rs0 += v0 + v1;
                rs1 += v2 + v3;
                __half h0, l0, h1, l1, h2, l2, h3, l3;
                split_f16(v0, h0, l0); split_f16(v1, h1, l1);
                split_f16(v2, h2, l2); split_f16(v3, h3, l3);
                size_t o0 = (size_t)r0 * Ln + n0 + cl;
                size_t o1 = (size_t)(r0 + 8) * Ln + n0 + cl;
                *(__half2*)&Ph[o0] = __halves2half2(h0, h1);
                *(__half2*)&Pl[o0] = __halves2half2(l0, l1);
                *(__half2*)&Ph[o1] = __halves2half2(h2, h3);
                *(__half2*)&Pl[o1] = __halves2half2(l2, l3);
            }
            rs0 += __shfl_xor_sync(0xffffffffu, rs0, 1);
            rs0 += __shfl_xor_sync(0xffffffffu, rs0, 2);
            rs1 += __shfl_xor_sync(0xffffffffu, rs1, 1);
            rs1 += __shfl_xor_sync(0xffffffffu, rs1, 2);
            if ((lane & 3) == 0) {
                atomicAdd(&S[r0], rs0);
                atomicAdd(&S[r0 + 8], rs1);
            }
        }
    } else {
        float* D = Dout + (size_t)b * Cn * Ln;
#pragma unroll
        for (int fm = 0; fm < 2; fm++)
#pragma unroll
            for (int fn = 0; fn < 8; fn++) {
                int r0 = m0 + wm * 32 + fm * 16 + (lane >> 2);
                int cl = wn * 64 + fn * 8 + (lane & 3) * 2;
                float i0 = lmp[cl], i1 = lmp[cl + 1];
                *(float2*)&D[(size_t)r0 * Ln + n0 + cl] =
                    make_float2(acc[fm][fn][0] * i0, acc[fm][fn][1] * i1);
                *(float2*)&D[(size_t)(r0 + 8) * Ln + n0 + cl] =
                    make_float2(acc[fm][fn][2] * i0, acc[fm][fn][3] * i1);
            }
    }
}

// ---------------------------------------------------------------------------
// Convert + transpose Q,K: [b][C][L] fp32 -> [b][L][C]
// Q -> single fp16; K -> fp16 hi/lo.
// ---------------------------------------------------------------------------
template <bool ISQ>
__global__ void convT_kernel(const float* __restrict__ X)
{
    __shared__ float tile[32][33];
    const int b = blockIdx.z, l0 = blockIdx.x * 32, c0 = blockIdx.y * 32;
    const int tx = threadIdx.x, ty = threadIdx.y;
#pragma unroll
    for (int r = 0; r < 32; r += 8)
        tile[ty + r][tx] = X[((size_t)b * Cn + c0 + ty + r) * Ln + l0 + tx];
    __syncthreads();
#pragma unroll
    for (int r = 0; r < 32; r += 8) {
        float v = tile[tx][ty + r];
        size_t idx = ((size_t)b * Ln + l0 + ty + r) * Cn + c0 + tx;
        if (ISQ) {
            g_Qt[idx] = __float2half(v);
        } else {
            __half h, l; split_f16(v, h, l);
            g_Kt_hi[idx] = h; g_Kt_lo[idx] = l;
        }
    }
}

// Convert V: fp32 -> fp16 of V*mask (mask folded in). Also zeroes g_S.
__global__ void convV_kernel(const float* __restrict__ V, const float* __restrict__ mask)
{
    if (blockIdx.x < (Bn * Ln) / 256)
        g_S[(size_t)blockIdx.x * 256 + threadIdx.x] = 0.0f;
    size_t idx = ((size_t)blockIdx.x * 256 + threadIdx.x) * 2;
    const int b = (int)(idx / ((size_t)Cn * Ln));
    const int j = (int)(idx % Ln);
    float2 v = *(const float2*)(V + idx);
    float2 m = *(const float2*)(mask + (size_t)b * Ln + j);
    *(__half2*)(g_V + idx) = __floats2half2_rn(v.x * m.x, v.y * m.y);
}

// ---------------------------------------------------------------------------
// attOut: attention output only.
//   attT[b][j][i] = (P_hi+P_lo)[i][j] * (1/S_i) * mask_j    (64x64 transpose)
// ---------------------------------------------------------------------------
__global__ __launch_bounds__(256) void attOut_kernel(float* __restrict__ AT,
                                                     const float* __restrict__ mask)
{
    __shared__ float tile[64][65];
    __shared__ float sinv[64], smask[64];
    const int b = blockIdx.z, j0 = blockIdx.x * 64, i0 = blockIdx.y * 64;
    const int t = threadIdx.x;
    const int r = t >> 2;            // 0..63 (row i0+r)
    const int seg = t & 3;           // 16 contiguous j's each

    if (t < 64)       sinv[t] = 1.0f / g_S[(size_t)b * Ln + i0 + t];
    else if (t < 128) smask[t - 64] = mask[(size_t)b * Ln + j0 + (t - 64)];
    __syncthreads();

    {
        size_t src = ((size_t)b * Ln + i0 + r) * Ln + j0 + seg * 16;
        uint4 h0 = *(const uint4*)&g_P_hi[src];
        uint4 h1 = *(const uint4*)&g_P_hi[src + 8];
        uint4 l0 = *(const uint4*)&g_P_lo[src];
        uint4 l1 = *(const uint4*)&g_P_lo[src + 8];
        const uint32_t* hw  = (const uint32_t*)&h0;
        const uint32_t* hw1 = (const uint32_t*)&h1;
        const uint32_t* lw  = (const uint32_t*)&l0;
        const uint32_t* lw1 = (const uint32_t*)&l1;
        const float inv = sinv[r];
#pragma unroll
        for (int k = 0; k < 4; k++) {
            float2 hp = __half22float2(*(__half2*)&hw[k]);
            float2 lp = __half22float2(*(__half2*)&lw[k]);
            tile[r][seg * 16 + 2 * k]     = (hp.x + lp.x) * inv * smask[seg * 16 + 2 * k];
            tile[r][seg * 16 + 2 * k + 1] = (hp.y + lp.y) * inv * smask[seg * 16 + 2 * k + 1];
        }
#pragma unroll
        for (int k = 0; k < 4; k++) {
            float2 hp = __half22float2(*(__half2*)&hw1[k]);
            float2 lp = __half22float2(*(__half2*)&lw1[k]);
            tile[r][seg * 16 + 8 + 2 * k]     = (hp.x + lp.x) * inv * smask[seg * 16 + 8 + 2 * k];
            tile[r][seg * 16 + 8 + 2 * k + 1] = (hp.y + lp.y) * inv * smask[seg * 16 + 8 + 2 * k + 1];
        }
    }
    __syncthreads();

    float o[16];
#pragma unroll
    for (int k = 0; k < 16; k++)
        o[k] = tile[seg * 16 + k][r];
    float* dst = AT + ((size_t)b * Ln + j0 + r) * Ln + i0 + seg * 16;
#pragma unroll
    for (int q = 0; q < 4; q++)
        *(float4*)&dst[q * 4] = *(float4*)&o[q * 4];
}

// ---------------------------------------------------------------------------
extern "C" void kernel_launch(void* const* d_in, const int* in_sizes, int n_in,
                              void* d_out, int out_size)
{
    const float* Q    = (const float*)d_in[0];
    const float* Kt   = (const float*)d_in[1];
    const float* V    = (const float*)d_in[2];
    const float* mask = (const float*)d_in[3];

    float* out  = (float*)d_out;                   // (B, C, L)
    float* attT = out + (size_t)Bn * Cn * Ln;      // (B, L, L)

    cudaFuncSetAttribute(mma_gemm_kernel<true>,
                         cudaFuncAttributeMaxDynamicSharedMemorySize, SMEM_BYTES);
    cudaFuncSetAttribute(mma_gemm_kernel<false>,
                         cudaFuncAttributeMaxDynamicSharedMemorySize, SMEM_BYTES);

    convT_kernel<true><<<dim3(Ln / 32, Cn / 32, Bn), dim3(32, 8)>>>(Q);
    convT_kernel<false><<<dim3(Ln / 32, Cn / 32, Bn), dim3(32, 8)>>>(Kt);
    convV_kernel<<<(int)(((size_t)Bn * Cn * Ln) / 512), 256>>>(V, mask);

    mma_gemm_kernel<true><<<dim3(Ln / 128, Ln / 128, Bn), 256, SMEM_BYTES>>>(nullptr, mask);
    mma_gemm_kernel<false><<<dim3(Cn / 128, Ln / 128, Bn), 256, SMEM_BYTES>>>(out, nullptr);
    attOut_kernel<<<dim3(Ln / 64, Ln / 64, Bn), 256>>>(attT, mask);
}

// round 12
// speedup vs baseline: 2.4257x; 1.5263x over previous
#include <cuda_runtime.h>
#include <cuda_bf16.h>
#include <cuda_fp16.h>
#include <math.h>
#include <stdint.h>

#define Bn 4
#define Cn 512
#define Ln 4096

// ---------------------------------------------------------------------------
// Scratch (static device globals; no allocation allowed)
// ---------------------------------------------------------------------------
__device__ float g_S[(size_t)Bn * Ln];                         // row sums of exp_un
__device__ __half g_Qt[(size_t)Bn * Ln * Cn];                  // fp16(Q^T) [b][i][c]
__device__ __half g_Kt[(size_t)Bn * Ln * Cn];                  // fp16(K^T) [b][j][c]
__device__ __half g_V[(size_t)Bn * Cn * Ln];                   // fp16(V*mask) [b][c][j]
__device__ __half g_P[(size_t)Bn * Ln * Ln];                   // fp16 exp_un [b][i][j]

// ---------------------------------------------------------------------------
// Base-ISA helpers (compute_103-safe: ldmatrix / mma.sync / cp.async)
// ---------------------------------------------------------------------------
__device__ __forceinline__ uint32_t smem_u32(const void* p) {
    uint32_t a;
    asm("{ .reg .u64 t; cvta.to.shared.u64 t, %1; cvt.u32.u64 %0, t; }" : "=r"(a) : "l"(p));
    return a;
}
__device__ __forceinline__ void ldsm_x4(uint32_t addr, uint32_t r[4]) {
    asm volatile("ldmatrix.sync.aligned.m8n8.x4.shared.b16 {%0,%1,%2,%3}, [%4];"
                 : "=r"(r[0]), "=r"(r[1]), "=r"(r[2]), "=r"(r[3]) : "r"(addr));
}
__device__ __forceinline__ void mma_f16(float d[4], const uint32_t a[4], const uint32_t b[2]) {
    asm volatile("mma.sync.aligned.m16n8k16.row.col.f32.f16.f16.f32 "
                 "{%0,%1,%2,%3}, {%4,%5,%6,%7}, {%8,%9}, {%0,%1,%2,%3};"
                 : "+f"(d[0]), "+f"(d[1]), "+f"(d[2]), "+f"(d[3])
                 : "r"(a[0]), "r"(a[1]), "r"(a[2]), "r"(a[3]), "r"(b[0]), "r"(b[1]));
}
#define CP16(d, s) asm volatile("cp.async.cg.shared.global [%0], [%1], 16;" :: "r"(d), "l"(s))
#define CP_COMMIT() asm volatile("cp.async.commit_group;" ::: "memory")
#define CP_WAIT1()  asm volatile("cp.async.wait_group 1;" ::: "memory")
#define CP_WAIT0()  asm volatile("cp.async.wait_group 0;" ::: "memory")

// ---------------------------------------------------------------------------
// smem geometry: 2 tiles (A, B), 128 rows x 32 fp16 = 64 B rows, XOR-swizzled.
// Triple buffered: 3 x 16 KB = 48 KB; regs capped at 128 -> 2 CTAs/SM.
// ---------------------------------------------------------------------------
#define SW(o) ((o) ^ (((o) >> 3) & 0x30))
#define ROWB 64
#define TILE_B (128 * ROWB)        // 8192
#define NSTAGE 3
#define BUFB (2 * TILE_B)          // 16384
#define LMOFF (NSTAGE * BUFB)      // 49152
#define SMEM_BYTES (LMOFF + 512)

// ---------------------------------------------------------------------------
// fp16 tensor-core GEMM: acc = A·B. 128x128 tile, BK=32, 256 threads,
// 3-stage cp.async pipeline.
// FIRST: P[i][j] = fp16( exp((Qt·Kt)*scale)*(mask+1e-6) ); row sums -> g_S
// !FIRST: out[c][i] = (Σ_j V'[c][j]·P[i][j]) / S_i
// ---------------------------------------------------------------------------
template <bool FIRST>
__global__ __launch_bounds__(256, 2) void mma_gemm_kernel(float* __restrict__ Dout,
                                                          const float* __restrict__ mask)
{
    constexpr int KTOT = FIRST ? Cn : Ln;
    constexpr int LD   = FIRST ? Cn : Ln;
    constexpr int NIT  = KTOT / 32;

    extern __shared__ char smem[];
    const uint32_t sbase = smem_u32(smem);
    const int tid = threadIdx.x;
    const int b = blockIdx.z;
    const int n0 = (FIRST ? blockIdx.x : blockIdx.y) * 128;
    const int m0 = (FIRST ? blockIdx.y : blockIdx.x) * 128;

    const __half* A  = (FIRST ? g_Qt : g_V) + ((size_t)b * (FIRST ? Ln : Cn) + m0) * LD;
    const __half* B  = (FIRST ? g_Kt : g_P) + ((size_t)b * Ln + n0) * LD;

    float* lmp = (float*)(smem + LMOFF);
    if (FIRST) {
        if (tid < 128) lmp[tid] = mask[(size_t)b * Ln + n0 + tid] + 1e-6f;
    } else {
        if (tid < 128) lmp[tid] = 1.0f / g_S[(size_t)b * Ln + n0 + tid];
    }

    const int lane = tid & 31, wid = tid >> 5;
    const int wm = wid & 3, wn = wid >> 2;
    const int quad = lane >> 3, qj = lane & 7;
    const int a_row = (quad & 1) * 8 + qj;
    const int a_kb  = (quad >> 1) * 16;
    const int b_row = (quad >> 1) * 8 + qj;
    const int b_kb  = (quad & 1) * 16;

    float acc[2][8][4];
#pragma unroll
    for (int fm = 0; fm < 2; fm++)
#pragma unroll
        for (int fn = 0; fn < 8; fn++)
#pragma unroll
            for (int e = 0; e < 4; e++) acc[fm][fn][e] = 0.0f;

    auto load_slab = [&](int buf, int it) {
        const uint32_t bb = sbase + buf * BUFB;
        const int k0 = it * 32;
#pragma unroll
        for (int t = 0; t < 2; t++) {
            int f = t * 256 + tid;
            int row = f >> 2, ch = f & 3;
            uint32_t doff = SW((uint32_t)(row * ROWB + ch * 16));
            size_t soff = (size_t)row * LD + k0 + ch * 8;
            CP16(bb + 0 * TILE_B + doff, A + soff);
            CP16(bb + 1 * TILE_B + doff, B + soff);
        }
        CP_COMMIT();
    };

    load_slab(0, 0);
    load_slab(1, 1);

    int buf = 0;
    for (int it = 0; it < NIT; it++) {
        if (it + 1 < NIT) { CP_WAIT1(); } else { CP_WAIT0(); }
        __syncthreads();
        if (it + 2 < NIT) {
            int nb = buf + 2; if (nb >= NSTAGE) nb -= NSTAGE;
            load_slab(nb, it + 2);
        }

        const uint32_t bb = sbase + buf * BUFB;
#pragma unroll
        for (int ks = 0; ks < 2; ks++) {
            uint32_t ar[2][4];
#pragma unroll
            for (int fm = 0; fm < 2; fm++) {
                uint32_t r = SW((uint32_t)((wm * 32 + fm * 16 + a_row) * ROWB + ks * 32 + a_kb));
                ldsm_x4(bb + 0 * TILE_B + r, ar[fm]);
            }
#pragma unroll
            for (int h = 0; h < 2; h++) {
                uint32_t br[4][2];
#pragma unroll
                for (int g = 0; g < 2; g++) {
                    uint32_t r = SW((uint32_t)((wn * 64 + h * 32 + g * 16 + b_row) * ROWB + ks * 32 + b_kb));
                    uint32_t t4[4];
                    ldsm_x4(bb + 1 * TILE_B + r, t4);
                    br[g * 2][0] = t4[0]; br[g * 2][1] = t4[1];
                    br[g * 2 + 1][0] = t4[2]; br[g * 2 + 1][1] = t4[3];
                }
#pragma unroll
                for (int fm = 0; fm < 2; fm++)
#pragma unroll
                    for (int fl = 0; fl < 4; fl++)
                        mma_f16(acc[fm][h * 4 + fl], ar[fm], br[fl]);
            }
        }
        if (++buf == NSTAGE) buf = 0;
    }

    const float scale = 0.04419417382415922f;      // 1/sqrt(512)
    if (FIRST) {
        float* S = g_S + (size_t)b * Ln;
        __half* P = g_P + (size_t)b * Ln * Ln;
#pragma unroll
        for (int fm = 0; fm < 2; fm++) {
            const int r0 = m0 + wm * 32 + fm * 16 + (lane >> 2);
            float rs0 = 0.0f, rs1 = 0.0f;
#pragma unroll
            for (int fn = 0; fn < 8; fn++) {
                int cl = wn * 64 + fn * 8 + (lane & 3) * 2;
                float me0 = lmp[cl], me1 = lmp[cl + 1];
                float v0 = expf(acc[fm][fn][0] * scale) * me0;
                float v1 = expf(acc[fm][fn][1] * scale) * me1;
                float v2 = expf(acc[fm][fn][2] * scale) * me0;
                float v3 = expf(acc[fm][fn][3] * scale) * me1;
                rs0 += v0 + v1;
                rs1 += v2 + v3;
                size_t o0 = (size_t)r0 * Ln + n0 + cl;
                size_t o1 = (size_t)(r0 + 8) * Ln + n0 + cl;
                *(__half2*)&P[o0] = __floats2half2_rn(v0, v1);
                *(__half2*)&P[o1] = __floats2half2_rn(v2, v3);
            }
            rs0 += __shfl_xor_sync(0xffffffffu, rs0, 1);
            rs0 += __shfl_xor_sync(0xffffffffu, rs0, 2);
            rs1 += __shfl_xor_sync(0xffffffffu, rs1, 1);
            rs1 += __shfl_xor_sync(0xffffffffu, rs1, 2);
            if ((lane & 3) == 0) {
                atomicAdd(&S[r0], rs0);
                atomicAdd(&S[r0 + 8], rs1);
            }
        }
    } else {
        float* D = Dout + (size_t)b * Cn * Ln;
#pragma unroll
        for (int fm = 0; fm < 2; fm++)
#pragma unroll
            for (int fn = 0; fn < 8; fn++) {
                int r0 = m0 + wm * 32 + fm * 16 + (lane >> 2);
                int cl = wn * 64 + fn * 8 + (lane & 3) * 2;
                float i0 = lmp[cl], i1 = lmp[cl + 1];
                *(float2*)&D[(size_t)r0 * Ln + n0 + cl] =
                    make_float2(acc[fm][fn][0] * i0, acc[fm][fn][1] * i1);
                *(float2*)&D[(size_t)(r0 + 8) * Ln + n0 + cl] =
                    make_float2(acc[fm][fn][2] * i0, acc[fm][fn][3] * i1);
            }
    }
}

// ---------------------------------------------------------------------------
// Convert + transpose Q,K: [b][C][L] fp32 -> [b][L][C] fp16
// ---------------------------------------------------------------------------
template <bool ISQ>
__global__ void convT_kernel(const float* __restrict__ X)
{
    __shared__ float tile[32][33];
    const int b = blockIdx.z, l0 = blockIdx.x * 32, c0 = blockIdx.y * 32;
    const int tx = threadIdx.x, ty = threadIdx.y;
#pragma unroll
    for (int r = 0; r < 32; r += 8)
        tile[ty + r][tx] = X[((size_t)b * Cn + c0 + ty + r) * Ln + l0 + tx];
    __syncthreads();
    __half* Dst = ISQ ? g_Qt : g_Kt;
#pragma unroll
    for (int r = 0; r < 32; r += 8) {
        size_t idx = ((size_t)b * Ln + l0 + ty + r) * Cn + c0 + tx;
        Dst[idx] = __float2half(tile[tx][ty + r]);
    }
}

// Convert V: fp32 -> fp16 of V*mask (mask folded in). Also zeroes g_S.
__global__ void convV_kernel(const float* __restrict__ V, const float* __restrict__ mask)
{
    if (blockIdx.x < (Bn * Ln) / 256)
        g_S[(size_t)blockIdx.x * 256 + threadIdx.x] = 0.0f;
    size_t idx = ((size_t)blockIdx.x * 256 + threadIdx.x) * 2;
    const int b = (int)(idx / ((size_t)Cn * Ln));
    const int j = (int)(idx % Ln);
    float2 v = *(const float2*)(V + idx);
    float2 m = *(const float2*)(mask + (size_t)b * Ln + j);
    *(__half2*)(g_V + idx) = __floats2half2_rn(v.x * m.x, v.y * m.y);
}

// ---------------------------------------------------------------------------
// attOut: attention output only.
//   attT[b][j][i] = P[i][j] * (1/S_i) * mask_j    (64x64 smem transpose)
// ---------------------------------------------------------------------------
__global__ __launch_bounds__(256) void attOut_kernel(float* __restrict__ AT,
                                                     const float* __restrict__ mask)
{
    __shared__ float tile[64][65];
    __shared__ float sinv[64], smask[64];
    const int b = blockIdx.z, j0 = blockIdx.x * 64, i0 = blockIdx.y * 64;
    const int t = threadIdx.x;
    const int r = t >> 2;            // 0..63 (row i0+r)
    const int seg = t & 3;           // 16 contiguous j's each

    if (t < 64)       sinv[t] = 1.0f / g_S[(size_t)b * Ln + i0 + t];
    else if (t < 128) smask[t - 64] = mask[(size_t)b * Ln + j0 + (t - 64)];
    __syncthreads();

    {
        size_t src = ((size_t)b * Ln + i0 + r) * Ln + j0 + seg * 16;
        uint4 p0 = *(const uint4*)&g_P[src];
        uint4 p1 = *(const uint4*)&g_P[src + 8];
        const uint32_t* pw  = (const uint32_t*)&p0;
        const uint32_t* pw1 = (const uint32_t*)&p1;
        const float inv = sinv[r];
#pragma unroll
        for (int k = 0; k < 4; k++) {
            float2 hp = __half22float2(*(__half2*)&pw[k]);
            tile[r][seg * 16 + 2 * k]     = hp.x * inv * smask[seg * 16 + 2 * k];
            tile[r][seg * 16 + 2 * k + 1] = hp.y * inv * smask[seg * 16 + 2 * k + 1];
        }
#pragma unroll
        for (int k = 0; k < 4; k++) {
            float2 hp = __half22float2(*(__half2*)&pw1[k]);
            tile[r][seg * 16 + 8 + 2 * k]     = hp.x * inv * smask[seg * 16 + 8 + 2 * k];
            tile[r][seg * 16 + 8 + 2 * k + 1] = hp.y * inv * smask[seg * 16 + 8 + 2 * k + 1];
        }
    }
    __syncthreads();

    float o[16];
#pragma unroll
    for (int k = 0; k < 16; k++)
        o[k] = tile[seg * 16 + k][r];
    float* dst = AT + ((size_t)b * Ln + j0 + r) * Ln + i0 + seg * 16;
#pragma unroll
    for (int q = 0; q < 4; q++)
        *(float4*)&dst[q * 4] = *(float4*)&o[q * 4];
}

// ---------------------------------------------------------------------------
extern "C" void kernel_launch(void* const* d_in, const int* in_sizes, int n_in,
                              void* d_out, int out_size)
{
    const float* Q    = (const float*)d_in[0];
    const float* Kt   = (const float*)d_in[1];
    const float* V    = (const float*)d_in[2];
    const float* mask = (const float*)d_in[3];

    float* out  = (float*)d_out;                   // (B, C, L)
    float* attT = out + (size_t)Bn * Cn * Ln;      // (B, L, L)

    cudaFuncSetAttribute(mma_gemm_kernel<true>,
                         cudaFuncAttributeMaxDynamicSharedMemorySize, SMEM_BYTES);
    cudaFuncSetAttribute(mma_gemm_kernel<false>,
                         cudaFuncAttributeMaxDynamicSharedMemorySize, SMEM_BYTES);

    convT_kernel<true><<<dim3(Ln / 32, Cn / 32, Bn), dim3(32, 8)>>>(Q);
    convT_kernel<false><<<dim3(Ln / 32, Cn / 32, Bn), dim3(32, 8)>>>(Kt);
    convV_kernel<<<(int)(((size_t)Bn * Cn * Ln) / 512), 256>>>(V, mask);

    mma_gemm_kernel<true><<<dim3(Ln / 128, Ln / 128, Bn), 256, SMEM_BYTES>>>(nullptr, mask);
    mma_gemm_kernel<false><<<dim3(Cn / 128, Ln / 128, Bn), 256, SMEM_BYTES>>>(out, nullptr);
    attOut_kernel<<<dim3(Ln / 64, Ln / 64, Bn), 256>>>(attT, mask);
}

// round 13
// speedup vs baseline: 2.6639x; 1.0982x over previous
#include <cuda_runtime.h>
#include <cuda_bf16.h>
#include <cuda_fp16.h>
#include <math.h>
#include <stdint.h>

#define Bn 4
#define Cn 512
#define Ln 4096

// ---------------------------------------------------------------------------
// Scratch (static device globals; no allocation allowed)
// ---------------------------------------------------------------------------
__device__ float g_S[(size_t)Bn * Ln];                         // row sums of exp_un
__device__ __half g_Qt[(size_t)Bn * Ln * Cn];                  // fp16(Q^T) [b][i][c]
__device__ __half g_Kt[(size_t)Bn * Ln * Cn];                  // fp16(K^T) [b][j][c]
__device__ __half g_V[(size_t)Bn * Cn * Ln];                   // fp16(V*mask) [b][c][j]
__device__ __half g_P[(size_t)Bn * Ln * Ln];                   // fp16 exp_un [b][i][j]

// ---------------------------------------------------------------------------
// Base-ISA helpers (compute_103-safe: ldmatrix / mma.sync / cp.async)
// ---------------------------------------------------------------------------
__device__ __forceinline__ uint32_t smem_u32(const void* p) {
    uint32_t a;
    asm("{ .reg .u64 t; cvta.to.shared.u64 t, %1; cvt.u32.u64 %0, t; }" : "=r"(a) : "l"(p));
    return a;
}
__device__ __forceinline__ void ldsm_x4(uint32_t addr, uint32_t r[4]) {
    asm volatile("ldmatrix.sync.aligned.m8n8.x4.shared.b16 {%0,%1,%2,%3}, [%4];"
                 : "=r"(r[0]), "=r"(r[1]), "=r"(r[2]), "=r"(r[3]) : "r"(addr));
}
__device__ __forceinline__ void mma_f16(float d[4], const uint32_t a[4], const uint32_t b[2]) {
    asm volatile("mma.sync.aligned.m16n8k16.row.col.f32.f16.f16.f32 "
                 "{%0,%1,%2,%3}, {%4,%5,%6,%7}, {%8,%9}, {%0,%1,%2,%3};"
                 : "+f"(d[0]), "+f"(d[1]), "+f"(d[2]), "+f"(d[3])
                 : "r"(a[0]), "r"(a[1]), "r"(a[2]), "r"(a[3]), "r"(b[0]), "r"(b[1]));
}
#define CP16(d, s) asm volatile("cp.async.cg.shared.global [%0], [%1], 16;" :: "r"(d), "l"(s))
#define CP_COMMIT() asm volatile("cp.async.commit_group;" ::: "memory")
#define CP_WAIT1()  asm volatile("cp.async.wait_group 1;" ::: "memory")
#define CP_WAIT0()  asm volatile("cp.async.wait_group 0;" ::: "memory")

// ---------------------------------------------------------------------------
// smem geometry: 2 tiles (A, B), 128 rows x 64 fp16 = 128 B rows, canonical
// SW128 swizzle. Triple buffered: 3 x 32 KB = 96 KB; 128-reg cap -> 2 CTAs/SM.
// ---------------------------------------------------------------------------
#define SW(o) ((o) ^ (((o) >> 3) & 0x70))
#define ROWB 128
#define TILE_B (128 * ROWB)        // 16384
#define NSTAGE 3
#define BUFB (2 * TILE_B)          // 32768
#define LMOFF (NSTAGE * BUFB)      // 98304
#define SMEM_BYTES (LMOFF + 512)

// ---------------------------------------------------------------------------
// fp16 tensor-core GEMM: acc = A·B. 128x128 tile, BK=64, 256 threads,
// 3-stage cp.async pipeline (one barrier per BK=64).
// FIRST: P[i][j] = fp16( exp((Qt·Kt)*scale)*(mask+1e-6) ); row sums -> g_S
// !FIRST: out[c][i] = (Σ_j V'[c][j]·P[i][j]) / S_i
// ---------------------------------------------------------------------------
template <bool FIRST>
__global__ __launch_bounds__(256, 2) void mma_gemm_kernel(float* __restrict__ Dout,
                                                          const float* __restrict__ mask)
{
    constexpr int KTOT = FIRST ? Cn : Ln;
    constexpr int LD   = FIRST ? Cn : Ln;
    constexpr int NIT  = KTOT / 64;

    extern __shared__ char smem[];
    const uint32_t sbase = smem_u32(smem);
    const int tid = threadIdx.x;
    const int b = blockIdx.z;
    const int n0 = (FIRST ? blockIdx.x : blockIdx.y) * 128;
    const int m0 = (FIRST ? blockIdx.y : blockIdx.x) * 128;

    const __half* A  = (FIRST ? g_Qt : g_V) + ((size_t)b * (FIRST ? Ln : Cn) + m0) * LD;
    const __half* B  = (FIRST ? g_Kt : g_P) + ((size_t)b * Ln + n0) * LD;

    float* lmp = (float*)(smem + LMOFF);
    if (FIRST) {
        if (tid < 128) lmp[tid] = mask[(size_t)b * Ln + n0 + tid] + 1e-6f;
    } else {
        if (tid < 128) lmp[tid] = 1.0f / g_S[(size_t)b * Ln + n0 + tid];
    }

    const int lane = tid & 31, wid = tid >> 5;
    const int wm = wid & 3, wn = wid >> 2;
    const int quad = lane >> 3, qj = lane & 7;
    const int a_row = (quad & 1) * 8 + qj;
    const int a_kb  = (quad >> 1) * 16;
    const int b_row = (quad >> 1) * 8 + qj;
    const int b_kb  = (quad & 1) * 16;

    float acc[2][8][4];
#pragma unroll
    for (int fm = 0; fm < 2; fm++)
#pragma unroll
        for (int fn = 0; fn < 8; fn++)
#pragma unroll
            for (int e = 0; e < 4; e++) acc[fm][fn][e] = 0.0f;

    auto load_slab = [&](int buf, int it) {
        const uint32_t bb = sbase + buf * BUFB;
        const int k0 = it * 64;
#pragma unroll
        for (int t = 0; t < 4; t++) {
            int f = t * 256 + tid;                 // 0..1023
            int row = f >> 3, ch = f & 7;          // 128 rows x 8 x 16B
            uint32_t doff = SW((uint32_t)(row * ROWB + ch * 16));
            size_t soff = (size_t)row * LD + k0 + ch * 8;
            CP16(bb + 0 * TILE_B + doff, A + soff);
            CP16(bb + 1 * TILE_B + doff, B + soff);
        }
        CP_COMMIT();
    };

    load_slab(0, 0);
    load_slab(1, 1);

    int buf = 0;
    for (int it = 0; it < NIT; it++) {
        if (it + 1 < NIT) { CP_WAIT1(); } else { CP_WAIT0(); }
        __syncthreads();
        if (it + 2 < NIT) {
            int nb = buf + 2; if (nb >= NSTAGE) nb -= NSTAGE;
            load_slab(nb, it + 2);
        }

        const uint32_t bb = sbase + buf * BUFB;
#pragma unroll
        for (int ks = 0; ks < 4; ks++) {
            uint32_t ar[2][4];
#pragma unroll
            for (int fm = 0; fm < 2; fm++) {
                uint32_t r = SW((uint32_t)((wm * 32 + fm * 16 + a_row) * ROWB + ks * 32 + a_kb));
                ldsm_x4(bb + 0 * TILE_B + r, ar[fm]);
            }
#pragma unroll
            for (int h = 0; h < 2; h++) {
                uint32_t br[4][2];
#pragma unroll
                for (int g = 0; g < 2; g++) {
                    uint32_t r = SW((uint32_t)((wn * 64 + h * 32 + g * 16 + b_row) * ROWB + ks * 32 + b_kb));
                    uint32_t t4[4];
                    ldsm_x4(bb + 1 * TILE_B + r, t4);
                    br[g * 2][0] = t4[0]; br[g * 2][1] = t4[1];
                    br[g * 2 + 1][0] = t4[2]; br[g * 2 + 1][1] = t4[3];
                }
#pragma unroll
                for (int fm = 0; fm < 2; fm++)
#pragma unroll
                    for (int fl = 0; fl < 4; fl++)
                        mma_f16(acc[fm][h * 4 + fl], ar[fm], br[fl]);
            }
        }
        if (++buf == NSTAGE) buf = 0;
    }

    const float scale = 0.04419417382415922f;      // 1/sqrt(512)
    if (FIRST) {
        float* S = g_S + (size_t)b * Ln;
        __half* P = g_P + (size_t)b * Ln * Ln;
#pragma unroll
        for (int fm = 0; fm < 2; fm++) {
            const int r0 = m0 + wm * 32 + fm * 16 + (lane >> 2);
            float rs0 = 0.0f, rs1 = 0.0f;
#pragma unroll
            for (int fn = 0; fn < 8; fn++) {
                int cl = wn * 64 + fn * 8 + (lane & 3) * 2;
                float me0 = lmp[cl], me1 = lmp[cl + 1];
                float v0 = expf(acc[fm][fn][0] * scale) * me0;
                float v1 = expf(acc[fm][fn][1] * scale) * me1;
                float v2 = expf(acc[fm][fn][2] * scale) * me0;
                float v3 = expf(acc[fm][fn][3] * scale) * me1;
                rs0 += v0 + v1;
                rs1 += v2 + v3;
                size_t o0 = (size_t)r0 * Ln + n0 + cl;
                size_t o1 = (size_t)(r0 + 8) * Ln + n0 + cl;
                *(__half2*)&P[o0] = __floats2half2_rn(v0, v1);
                *(__half2*)&P[o1] = __floats2half2_rn(v2, v3);
            }
            rs0 += __shfl_xor_sync(0xffffffffu, rs0, 1);
            rs0 += __shfl_xor_sync(0xffffffffu, rs0, 2);
            rs1 += __shfl_xor_sync(0xffffffffu, rs1, 1);
            rs1 += __shfl_xor_sync(0xffffffffu, rs1, 2);
            if ((lane & 3) == 0) {
                atomicAdd(&S[r0], rs0);
                atomicAdd(&S[r0 + 8], rs1);
            }
        }
    } else {
        float* D = Dout + (size_t)b * Cn * Ln;
#pragma unroll
        for (int fm = 0; fm < 2; fm++)
#pragma unroll
            for (int fn = 0; fn < 8; fn++) {
                int r0 = m0 + wm * 32 + fm * 16 + (lane >> 2);
                int cl = wn * 64 + fn * 8 + (lane & 3) * 2;
                float i0 = lmp[cl], i1 = lmp[cl + 1];
                *(float2*)&D[(size_t)r0 * Ln + n0 + cl] =
                    make_float2(acc[fm][fn][0] * i0, acc[fm][fn][1] * i1);
                *(float2*)&D[(size_t)(r0 + 8) * Ln + n0 + cl] =
                    make_float2(acc[fm][fn][2] * i0, acc[fm][fn][3] * i1);
            }
    }
}

// ---------------------------------------------------------------------------
// Convert + transpose Q,K: [b][C][L] fp32 -> [b][L][C] fp16
// ---------------------------------------------------------------------------
template <bool ISQ>
__global__ void convT_kernel(const float* __restrict__ X)
{
    __shared__ float tile[32][33];
    const int b = blockIdx.z, l0 = blockIdx.x * 32, c0 = blockIdx.y * 32;
    const int tx = threadIdx.x, ty = threadIdx.y;
#pragma unroll
    for (int r = 0; r < 32; r += 8)
        tile[ty + r][tx] = X[((size_t)b * Cn + c0 + ty + r) * Ln + l0 + tx];
    __syncthreads();
    __half* Dst = ISQ ? g_Qt : g_Kt;
#pragma unroll
    for (int r = 0; r < 32; r += 8) {
        size_t idx = ((size_t)b * Ln + l0 + ty + r) * Cn + c0 + tx;
        Dst[idx] = __float2half(tile[tx][ty + r]);
    }
}

// Convert V: fp32 -> fp16 of V*mask (mask folded in). Also zeroes g_S.
__global__ void convV_kernel(const float* __restrict__ V, const float* __restrict__ mask)
{
    if (blockIdx.x < (Bn * Ln) / 256)
        g_S[(size_t)blockIdx.x * 256 + threadIdx.x] = 0.0f;
    size_t idx = ((size_t)blockIdx.x * 256 + threadIdx.x) * 2;
    const int b = (int)(idx / ((size_t)Cn * Ln));
    const int j = (int)(idx % Ln);
    float2 v = *(const float2*)(V + idx);
    float2 m = *(const float2*)(mask + (size_t)b * Ln + j);
    *(__half2*)(g_V + idx) = __floats2half2_rn(v.x * m.x, v.y * m.y);
}

// ---------------------------------------------------------------------------
// attOut: attention output only.
//   attT[b][j][i] = P[i][j] * (1/S_i) * mask_j    (64x64 smem transpose)
// ---------------------------------------------------------------------------
__global__ __launch_bounds__(256) void attOut_kernel(float* __restrict__ AT,
                                                     const float* __restrict__ mask)
{
    __shared__ float tile[64][65];
    __shared__ float sinv[64], smask[64];
    const int b = blockIdx.z, j0 = blockIdx.x * 64, i0 = blockIdx.y * 64;
    const int t = threadIdx.x;
    const int r = t >> 2;            // 0..63 (row i0+r)
    const int seg = t & 3;           // 16 contiguous j's each

    if (t < 64)       sinv[t] = 1.0f / g_S[(size_t)b * Ln + i0 + t];
    else if (t < 128) smask[t - 64] = mask[(size_t)b * Ln + j0 + (t - 64)];
    __syncthreads();

    {
        size_t src = ((size_t)b * Ln + i0 + r) * Ln + j0 + seg * 16;
        uint4 p0 = *(const uint4*)&g_P[src];
        uint4 p1 = *(const uint4*)&g_P[src + 8];
        const uint32_t* pw  = (const uint32_t*)&p0;
        const uint32_t* pw1 = (const uint32_t*)&p1;
        const float inv = sinv[r];
#pragma unroll
        for (int k = 0; k < 4; k++) {
            float2 hp = __half22float2(*(__half2*)&pw[k]);
            tile[r][seg * 16 + 2 * k]     = hp.x * inv * smask[seg * 16 + 2 * k];
            tile[r][seg * 16 + 2 * k + 1] = hp.y * inv * smask[seg * 16 + 2 * k + 1];
        }
#pragma unroll
        for (int k = 0; k < 4; k++) {
            float2 hp = __half22float2(*(__half2*)&pw1[k]);
            tile[r][seg * 16 + 8 + 2 * k]     = hp.x * inv * smask[seg * 16 + 8 + 2 * k];
            tile[r][seg * 16 + 8 + 2 * k + 1] = hp.y * inv * smask[seg * 16 + 8 + 2 * k + 1];
        }
    }
    __syncthreads();

    float o[16];
#pragma unroll
    for (int k = 0; k < 16; k++)
        o[k] = tile[seg * 16 + k][r];
    float* dst = AT + ((size_t)b * Ln + j0 + r) * Ln + i0 + seg * 16;
#pragma unroll
    for (int q = 0; q < 4; q++)
        *(float4*)&dst[q * 4] = *(float4*)&o[q * 4];
}

// ---------------------------------------------------------------------------
extern "C" void kernel_launch(void* const* d_in, const int* in_sizes, int n_in,
                              void* d_out, int out_size)
{
    const float* Q    = (const float*)d_in[0];
    const float* Kt   = (const float*)d_in[1];
    const float* V    = (const float*)d_in[2];
    const float* mask = (const float*)d_in[3];

    float* out  = (float*)d_out;                   // (B, C, L)
    float* attT = out + (size_t)Bn * Cn * Ln;      // (B, L, L)

    cudaFuncSetAttribute(mma_gemm_kernel<true>,
                         cudaFuncAttributeMaxDynamicSharedMemorySize, SMEM_BYTES);
    cudaFuncSetAttribute(mma_gemm_kernel<false>,
                         cudaFuncAttributeMaxDynamicSharedMemorySize, SMEM_BYTES);

    convT_kernel<true><<<dim3(Ln / 32, Cn / 32, Bn), dim3(32, 8)>>>(Q);
    convT_kernel<false><<<dim3(Ln / 32, Cn / 32, Bn), dim3(32, 8)>>>(Kt);
    convV_kernel<<<(int)(((size_t)Bn * Cn * Ln) / 512), 256>>>(V, mask);

    mma_gemm_kernel<true><<<dim3(Ln / 128, Ln / 128, Bn), 256, SMEM_BYTES>>>(nullptr, mask);
    mma_gemm_kernel<false><<<dim3(Cn / 128, Ln / 128, Bn), 256, SMEM_BYTES>>>(out, nullptr);
    attOut_kernel<<<dim3(Ln / 64, Ln / 64, Bn), 256>>>(attT, mask);
}